// round 9
// baseline (speedup 1.0000x reference)
#include <cuda_runtime.h>
#include <cuda_bf16.h>
#include <cuda_fp8.h>
#include <mma.h>
#include <math.h>
#include <stdint.h>

using namespace nvcuda;

// ---------------- problem constants ----------------
#define BB 8
#define T1C 32
#define T2C 32
#define JC 33
#define KSEG 9
#define NN 8448
#define EC 256
#define HC 512
#define UC 1024
#define GHC 2048
#define VC 8000
#define START_ID 8001
#define GIN_ROWS 2376
#define GIN_ROWS_PAD 2432

typedef __nv_bfloat16 bf16;
typedef __nv_bfloat162 bf162;

#define WSCALE 8.0f
#define WSCALE_INV 0.125f

// ---------------- device scratch ----------------
__device__ uint8_t d_X1f8[NN * 1024];         // [h0 | h1] per row, e4m3
__device__ bf16  d_X1b[NN * HC];              // h1 bf16 (for fc GEMM)
__device__ float d_c0[NN * HC];
__device__ float d_c1[NN * HC];
__device__ bf16  d_fco[2 * NN * EC];          // double-buffered across steps
__device__ float d_gin[GIN_ROWS_PAD * GHC];
__device__ float d_gctx[256 * GHC];
__device__ bf16  d_ctxb[256 * HC];
__device__ float d_hinit[2 * BB * HC];
__device__ float d_cinit[2 * BB * HC];
__device__ float d_cum[NN];
__device__ float d_b0p[GHC];
__device__ float d_b1p[GHC];
__device__ int   d_ginoff[GIN_ROWS_PAD];
__device__ int   d_ctxoff[256];
__device__ int   d_tgttok[GIN_ROWS];
__device__ uint8_t d_Whh0f8[GHC * HC];        // e4m3, x8 scaled, row-permuted [h*4+gate]
__device__ uint8_t d_W1catf8[GHC * 1024];     // e4m3, x8 scaled, row-permuted
__device__ bf16 d_Wfcb[EC * HC];
__device__ bf16 d_Woutb[VC * EC];
__device__ bf16 d_embb[(VC + 2) * EC];
__device__ bf16 d_Wih0b[GHC * (EC + HC)];     // bf16, row-permuted (for gin/gctx tables)
__device__ bf16 d_Wphb[HC * UC];
__device__ bf16 d_encOb[T1C * BB * UC];

__device__ __forceinline__ float tanha(float x) {
    float y; asm("tanh.approx.f32 %0, %1;" : "=f"(y) : "f"(x)); return y;
}
__device__ __forceinline__ float sigfast(float x) { return 0.5f * tanha(0.5f * x) + 0.5f; }

__device__ __forceinline__ void cpa16(void* dst, const void* src) {
    uint32_t d = (uint32_t)__cvta_generic_to_shared(dst);
    asm volatile("cp.async.cg.shared.global [%0], [%1], 16;\n" :: "r"(d), "l"(src));
}
__device__ __forceinline__ void cpa_commit() { asm volatile("cp.async.commit_group;\n"); }
template <int N> __device__ __forceinline__ void cpa_wait() {
    asm volatile("cp.async.wait_group %0;\n" :: "n"(N));
}
__device__ __forceinline__ void ldsm4(uint32_t& r0, uint32_t& r1, uint32_t& r2, uint32_t& r3,
                                      uint32_t addr) {
    asm volatile("ldmatrix.sync.aligned.m8n8.x4.shared.b16 {%0,%1,%2,%3}, [%4];"
                 : "=r"(r0), "=r"(r1), "=r"(r2), "=r"(r3) : "r"(addr));
}
__device__ __forceinline__ uint8_t f2e4m3(float x) {
    return (uint8_t)__nv_cvt_float_to_fp8(x, __NV_SATFINITE, __NV_E4M3);
}

// ---------------- prologue kernels ----------------
__global__ void cvt_kernel(const float* __restrict__ src, bf16* __restrict__ dst, int n4) {
    int i = blockIdx.x * blockDim.x + threadIdx.x;
    if (i >= n4) return;
    float4 v = ((const float4*)src)[i];
    bf162* d = (bf162*)dst + i * 2;
    d[0] = __floats2bfloat162_rn(v.x, v.y);
    d[1] = __floats2bfloat162_rn(v.z, v.w);
}

// permuted bf16 convert: dst[(h*4+gate)*ldw + c] = W[(gate*512+h)*ldw + c]
__global__ void wperm_kernel(const float* __restrict__ W, bf16* __restrict__ dst, int ldw) {
    int idx = blockIdx.x * blockDim.x + threadIdx.x;
    if (idx >= GHC * ldw) return;
    int np = idx / ldw, c = idx - np * ldw;
    int h = np >> 2, gate = np & 3;
    dst[idx] = __float2bfloat16(W[(size_t)(gate * HC + h) * ldw + c]);
}

// permuted f8 convert with x8 scale
__global__ void wperm_f8_kernel(const float* __restrict__ W, uint8_t* __restrict__ dst, int ldw) {
    int idx = blockIdx.x * blockDim.x + threadIdx.x;
    if (idx >= GHC * ldw) return;
    int np = idx / ldw, c = idx - np * ldw;
    int h = np >> 2, gate = np & 3;
    dst[idx] = f2e4m3(W[(size_t)(gate * HC + h) * ldw + c] * WSCALE);
}

__global__ void w1catperm_f8_kernel(const float* __restrict__ Wih1, const float* __restrict__ Whh1) {
    int idx = blockIdx.x * blockDim.x + threadIdx.x;
    if (idx >= GHC * 1024) return;
    int np = idx >> 10, c = idx & 1023;
    int o = (np & 3) * HC + (np >> 2);
    float v = (c < HC) ? Wih1[(size_t)o * HC + c] : Whh1[(size_t)o * HC + (c - HC)];
    d_W1catf8[idx] = f2e4m3(v * WSCALE);
}

__global__ void biasperm_kernel(const float* __restrict__ bih0, const float* __restrict__ bhh0,
                                const float* __restrict__ bih1, const float* __restrict__ bhh1) {
    int idx = blockIdx.x * blockDim.x + threadIdx.x;
    if (idx >= GHC) return;
    int o = (idx & 3) * HC + (idx >> 2);
    d_b0p[idx] = bih0[o] + bhh0[o];
    d_b1p[idx] = bih1[o] + bhh1[o];
}

__global__ void tok_kernel(const int* __restrict__ prev) {
    int r = blockIdx.x * blockDim.x + threadIdx.x;
    if (r >= GIN_ROWS_PAD) return;
    if (r < GIN_ROWS) {
        int k = r / (BB * JC);
        int bj = r - k * (BB * JC);
        int b = bj / JC;
        int j = bj - b * JC;
        int pin = j + k - 1; if (pin > T2C - 1) pin = T2C - 1;
        int tin = (k == 0) ? START_ID : prev[b * T2C + pin];
        d_ginoff[r] = tin * EC;
        int pt = j + k; if (pt > T2C - 1) pt = T2C - 1;
        d_tgttok[r] = prev[b * T2C + pt];
    } else {
        d_ginoff[r] = 0;
    }
}

__global__ void ctxoff_kernel() {
    int r = threadIdx.x;
    if (r < 256) {
        int b = r / T1C, t1 = r - b * T1C;
        d_ctxoff[r] = t1 * (BB * UC) + b * UC;
    }
}

__global__ void hcinit_kernel(const float* __restrict__ ench, const float* __restrict__ encc,
                              const float* __restrict__ Wph, const float* __restrict__ bph,
                              const float* __restrict__ Wpc, const float* __restrict__ bpc) {
    int idx = blockIdx.x * blockDim.x + threadIdx.x;
    if (idx >= 2 * BB * HC) return;
    int l = idx / (BB * HC);
    int b = (idx / HC) % BB;
    int h = idx % HC;
    const float4* eh = (const float4*)(ench + l * BB * UC + b * UC);
    const float4* ec = (const float4*)(encc + l * BB * UC + b * UC);
    const float4* wh = (const float4*)(Wph + (size_t)h * UC);
    const float4* wc = (const float4*)(Wpc + (size_t)h * UC);
    float sh = 0.f, sc = 0.f;
    for (int u = 0; u < UC / 4; u++) {
        float4 a = eh[u], w = wh[u];
        sh += a.x * w.x + a.y * w.y + a.z * w.z + a.w * w.w;
        float4 a2 = ec[u], w2 = wc[u];
        sc += a2.x * w2.x + a2.y * w2.y + a2.z * w2.z + a2.w * w2.w;
    }
    d_hinit[idx] = sh + bph[h];
    d_cinit[idx] = sc + bpc[h];
}

__global__ void initX_kernel() {
    int idx = blockIdx.x * blockDim.x + threadIdx.x;
    if (idx >= NN * HC) return;
    int n = idx >> 9, h = idx & 511;
    int b = n / (T1C * JC);
    float h0v = d_hinit[b * HC + h];
    float h1v = d_hinit[BB * HC + b * HC + h];
    d_X1f8[(size_t)n * 1024 + h]       = f2e4m3(h0v);
    d_X1f8[(size_t)n * 1024 + 512 + h] = f2e4m3(h1v);
    d_X1b[(size_t)n * HC + h] = __float2bfloat16(h1v);
    d_c0[idx] = d_cinit[b * HC + h];
    d_c1[idx] = d_cinit[BB * HC + b * HC + h];
    if (h == 0) d_cum[n] = 0.f;
}

// ---------------- FP8 TN GEMM + fused LSTM cell ----------------
// C[m,n] = (sum_k A[m,k]*B[n,k]) * 1/8 + epi; EPI: 4 CELL0 (+gin+gctx), 5 CELL1 (+e1[n])
#define F8_SAS 80
#define F8_STAGE (128 * F8_SAS)
#define F8_GSM 67584
template <int EPI>
__global__ void __launch_bounds__(256, 2)
gemm_f8(const uint8_t* __restrict__ A, int lda,
        const uint8_t* __restrict__ Bm, int ldb, int K,
        const float* __restrict__ e1, const float* __restrict__ e2, int kstep,
        float* __restrict__ cptr, uint8_t* __restrict__ hf8, bf16* __restrict__ hbf) {
    extern __shared__ char smraw[];
    uint8_t* sA = (uint8_t*)smraw;
    uint8_t* sB = sA + 2 * F8_STAGE;
    float* sC = (float*)smraw;
    uint32_t sA_u = (uint32_t)__cvta_generic_to_shared(sA);
    uint32_t sB_u = (uint32_t)__cvta_generic_to_shared(sB);

    int tid = threadIdx.x, wid = tid >> 5, lane = tid & 31;
    int m0 = blockIdx.y * 128, n0 = blockIdx.x * 128;
    int wm = wid & 1, wn = wid >> 1;

    float acc[4][4][4];
#pragma unroll
    for (int mi = 0; mi < 4; mi++)
#pragma unroll
        for (int nt = 0; nt < 4; nt++)
#pragma unroll
            for (int r = 0; r < 4; r++) acc[mi][nt][r] = 0.0f;

    int nk = K >> 6;

    int q = lane >> 3, p = lane & 7;
    int lrow = p + (q & 1) * 8;
    int lcol = (q >> 1) * 16;

#define F8_ISSUE(S)                                                                      \
    {                                                                                    \
        int buf_ = (S) & 1;                                                              \
        int k0_ = (S) << 6;                                                              \
        _Pragma("unroll")                                                                \
        for (int i_ = 0; i_ < 2; i_++) {                                                 \
            int idx_ = tid + i_ * 256;                                                   \
            int r_ = idx_ >> 2, c_ = idx_ & 3;                                           \
            cpa16(sA + buf_ * F8_STAGE + r_ * F8_SAS + c_ * 16,                          \
                  A + (size_t)(m0 + r_) * lda + k0_ + c_ * 16);                          \
        }                                                                                \
        _Pragma("unroll")                                                                \
        for (int i_ = 0; i_ < 2; i_++) {                                                 \
            int idx_ = tid + i_ * 256;                                                   \
            int r_ = idx_ >> 2, c_ = idx_ & 3;                                           \
            cpa16(sB + buf_ * F8_STAGE + r_ * F8_SAS + c_ * 16,                          \
                  Bm + (size_t)(n0 + r_) * ldb + k0_ + c_ * 16);                         \
        }                                                                                \
        cpa_commit();                                                                    \
    }

    F8_ISSUE(0);
    for (int s = 0; s < nk; s++) {
        cpa_wait<0>();
        __syncthreads();
        if (s + 1 < nk) F8_ISSUE(s + 1);
        int buf = s & 1;
        uint32_t aBase = sA_u + buf * F8_STAGE;
        uint32_t bBase = sB_u + buf * F8_STAGE;
#pragma unroll
        for (int kk = 0; kk < 2; kk++) {
            uint32_t am[4][4];
#pragma unroll
            for (int mi = 0; mi < 4; mi++)
                ldsm4(am[mi][0], am[mi][1], am[mi][2], am[mi][3],
                      aBase + (uint32_t)(wm * 64 + mi * 16 + lrow) * F8_SAS + kk * 32 + lcol);
            uint32_t bmx[2][4];
#pragma unroll
            for (int bi = 0; bi < 2; bi++)
                ldsm4(bmx[bi][0], bmx[bi][1], bmx[bi][2], bmx[bi][3],
                      bBase + (uint32_t)(wn * 32 + bi * 16 + lrow) * F8_SAS + kk * 32 + lcol);
#pragma unroll
            for (int mi = 0; mi < 4; mi++)
#pragma unroll
                for (int nt = 0; nt < 4; nt++) {
                    int bi = nt >> 1, sel = nt & 1;
                    uint32_t b0 = bmx[bi][sel ? 1 : 0];
                    uint32_t b1 = bmx[bi][sel ? 3 : 2];
                    asm volatile(
                        "mma.sync.aligned.m16n8k32.row.col.f32.e4m3.e4m3.f32 "
                        "{%0,%1,%2,%3}, {%4,%5,%6,%7}, {%8,%9}, {%0,%1,%2,%3};"
                        : "+f"(acc[mi][nt][0]), "+f"(acc[mi][nt][1]),
                          "+f"(acc[mi][nt][2]), "+f"(acc[mi][nt][3])
                        : "r"(am[mi][0]), "r"(am[mi][1]), "r"(am[mi][2]), "r"(am[mi][3]),
                          "r"(b0), "r"(b1));
                }
        }
    }
    __syncthreads();

    {   // accumulator -> sC (m16n8 f32 fragment layout)
        int rbase = wm * 64 + (lane >> 2);
        int cbase = wn * 32 + (lane & 3) * 2;
#pragma unroll
        for (int mi = 0; mi < 4; mi++)
#pragma unroll
            for (int nt = 0; nt < 4; nt++) {
                int rr = rbase + mi * 16;
                int cc = cbase + nt * 8;
                sC[rr * 132 + cc]           = acc[mi][nt][0];
                sC[rr * 132 + cc + 1]       = acc[mi][nt][1];
                sC[(rr + 8) * 132 + cc]     = acc[mi][nt][2];
                sC[(rr + 8) * 132 + cc + 1] = acc[mi][nt][3];
            }
    }
    __syncthreads();

#pragma unroll
    for (int i = 0; i < 16; i++) {
        int idx = tid + i * 256;
        int r = idx >> 5, c4 = idx & 31;
        float4 v = *(float4*)(sC + r * 132 + c4 * 4);
        v.x *= WSCALE_INV; v.y *= WSCALE_INV; v.z *= WSCALE_INV; v.w *= WSCALE_INV;
        int m = m0 + r;
        int nb = n0 + c4 * 4;
        if (EPI == 5) {
            float4 bb = *(const float4*)(e1 + nb);
            v.x += bb.x; v.y += bb.y; v.z += bb.z; v.w += bb.w;
        } else {
            int b = m / (T1C * JC);
            int rem = m - b * (T1C * JC);
            int t1 = rem / JC;
            int j = rem - t1 * JC;
            const float* gi = e1 + (size_t)((kstep * BB + b) * JC + j) * GHC + nb;
            const float* gc = e2 + (size_t)(b * T1C + t1) * GHC + nb;
            float4 a1 = *(const float4*)gi;
            float4 a2 = *(const float4*)gc;
            v.x += a1.x + a2.x; v.y += a1.y + a2.y; v.z += a1.z + a2.z; v.w += a1.w + a2.w;
        }
        int h = nb >> 2;
        size_t cix = (size_t)m * HC + h;
        float cold = cptr[cix];
        float cn = sigfast(v.y) * cold + sigfast(v.x) * tanha(v.z);
        cptr[cix] = cn;
        float hv = sigfast(v.w) * tanha(cn);
        hf8[(size_t)m * 1024 + h] = f2e4m3(hv);
        if (EPI == 5) hbf[(size_t)m * HC + h] = __float2bfloat16(hv);
    }
#undef F8_ISSUE
}

// ---------------- bf16 TN GEMM (R3 config) — prologue + fc ----------------
#define SASTRIDE 40
#define GSM_BYTES 67584
template <int EPI, bool GATHER, bool OBF>
__launch_bounds__(256)
__global__ void gemm_bf(const bf16* __restrict__ A, int lda,
                        const bf16* __restrict__ Bm, int ldb,
                        void* __restrict__ Cv, int ldc, int K,
                        const int* __restrict__ rowoff,
                        const float* __restrict__ e1) {
    extern __shared__ char smraw[];
    bf16* sA = (bf16*)smraw;
    bf16* sB = sA + 2 * 128 * SASTRIDE;
    float* sC = (float*)smraw;

    int tid = threadIdx.x;
    int m0 = blockIdx.y * 128, n0 = blockIdx.x * 128;
    int wid = tid >> 5;
    int wm = wid & 1, wn = wid >> 1;

    wmma::fragment<wmma::accumulator, 16, 16, 16, float> acc[4][2];
#pragma unroll
    for (int mi = 0; mi < 4; mi++)
#pragma unroll
        for (int ni = 0; ni < 2; ni++) wmma::fill_fragment(acc[mi][ni], 0.0f);

    int nk = K >> 5;

#define GEMM_ISSUE(S)                                                                    \
    {                                                                                    \
        int buf_ = (S) & 1;                                                              \
        int k0_ = (S) << 5;                                                              \
        _Pragma("unroll")                                                                \
        for (int i_ = 0; i_ < 2; i_++) {                                                 \
            int idx_ = tid + i_ * 256;                                                   \
            int r_ = idx_ >> 2, c_ = idx_ & 3;                                           \
            const bf16* src_ = GATHER ? (A + rowoff[m0 + r_] + k0_ + c_ * 8)             \
                                      : (A + (size_t)(m0 + r_) * lda + k0_ + c_ * 8);    \
            cpa16(sA + buf_ * (128 * SASTRIDE) + r_ * SASTRIDE + c_ * 8, src_);          \
        }                                                                                \
        _Pragma("unroll")                                                                \
        for (int i_ = 0; i_ < 2; i_++) {                                                 \
            int idx_ = tid + i_ * 256;                                                   \
            int r_ = idx_ >> 2, c_ = idx_ & 3;                                           \
            cpa16(sB + buf_ * (128 * SASTRIDE) + r_ * SASTRIDE + c_ * 8,                 \
                  Bm + (size_t)(n0 + r_) * ldb + k0_ + c_ * 8);                          \
        }                                                                                \
        cpa_commit();                                                                    \
    }

    GEMM_ISSUE(0);
    for (int s = 0; s < nk; s++) {
        cpa_wait<0>();
        __syncthreads();
        if (s + 1 < nk) GEMM_ISSUE(s + 1);
        int buf = s & 1;
        const bf16* a_base = sA + buf * (128 * SASTRIDE);
        const bf16* b_base = sB + buf * (128 * SASTRIDE);
#pragma unroll
        for (int kk = 0; kk < 2; kk++) {
            wmma::fragment<wmma::matrix_a, 16, 16, 16, bf16, wmma::row_major> af[4];
            wmma::fragment<wmma::matrix_b, 16, 16, 16, bf16, wmma::col_major> bfr[2];
#pragma unroll
            for (int mi = 0; mi < 4; mi++)
                wmma::load_matrix_sync(af[mi], a_base + (wm * 64 + mi * 16) * SASTRIDE + kk * 16, SASTRIDE);
#pragma unroll
            for (int ni = 0; ni < 2; ni++)
                wmma::load_matrix_sync(bfr[ni], b_base + (wn * 32 + ni * 16) * SASTRIDE + kk * 16, SASTRIDE);
#pragma unroll
            for (int mi = 0; mi < 4; mi++)
#pragma unroll
                for (int ni = 0; ni < 2; ni++)
                    wmma::mma_sync(acc[mi][ni], af[mi], bfr[ni], acc[mi][ni]);
        }
    }
    __syncthreads();
#pragma unroll
    for (int mi = 0; mi < 4; mi++)
#pragma unroll
        for (int ni = 0; ni < 2; ni++)
            wmma::store_matrix_sync(sC + (wm * 64 + mi * 16) * 132 + wn * 32 + ni * 16,
                                    acc[mi][ni], 132, wmma::mem_row_major);
    __syncthreads();

#pragma unroll
    for (int i = 0; i < 16; i++) {
        int idx = tid + i * 256;
        int r = idx >> 5, c4 = idx & 31;
        float4 v = *(float4*)(sC + r * 132 + c4 * 4);
        int m = m0 + r;
        int nb = n0 + c4 * 4;
        if (EPI == 1) {
            float4 bb = *(const float4*)(e1 + nb);
            v.x += bb.x; v.y += bb.y; v.z += bb.z; v.w += bb.w;
        }
        if (OBF) {
            bf162* pp = (bf162*)((bf16*)Cv + (size_t)m * ldc + nb);
            pp[0] = __floats2bfloat162_rn(v.x, v.y);
            pp[1] = __floats2bfloat162_rn(v.z, v.w);
        } else {
            *(float4*)((float*)Cv + (size_t)m * ldc + nb) = v;
        }
    }
#undef GEMM_ISSUE
}

// ---------------- fused Wout GEMM (wmma bf16) + online logsumexp ----------------
#define WA_STRIDE 264
#define WB_STRIDE 264
#define WOUT_SMEM_BYTES (64 * WA_STRIDE * 2 + 2 * 64 * WB_STRIDE * 2 + 64 * 72 * 4 + 64 * 5 * 4)
__launch_bounds__(256)
__global__ void wout_lse(const bf16* __restrict__ fco, const bf16* __restrict__ Wout,
                         const float* __restrict__ bout, const int* __restrict__ tgttok,
                         float* __restrict__ cum, float* __restrict__ outp, int kstep) {
    extern __shared__ char smraw[];
    bf16* A_s = (bf16*)smraw;
    bf16* B_s = A_s + 64 * WA_STRIDE;
    float* C_s = (float*)(B_s + 2 * 64 * WB_STRIDE);
    float* rM = C_s + 64 * 72;
    float* rS = rM + 64;
    float* rE = rS + 64;
    float* rT = rE + 64;
    int* rTgt = (int*)(rT + 64);

    int tid = threadIdx.x;
    int m0 = blockIdx.x * 64;

#pragma unroll
    for (int i = 0; i < 8; i++) {
        int idx = tid + i * 256;
        int r = idx >> 5, c = idx & 31;
        *(uint4*)(A_s + r * WA_STRIDE + c * 8) = *(const uint4*)(fco + (size_t)(m0 + r) * EC + c * 8);
    }
    if (tid < 64) {
        int n = m0 + tid;
        int b = n / (T1C * JC);
        int rem = n - b * (T1C * JC);
        int j = rem % JC;
        rTgt[tid] = tgttok[(kstep * BB + b) * JC + j];
        rM[tid] = -1e30f; rS[tid] = 0.f; rE[tid] = 0.f; rT[tid] = 0.f;
    }

    int wid = tid >> 5;
    int wm = wid & 1, wn = wid >> 1;

#define WOUT_ISSUE(S)                                                                  \
    {                                                                                  \
        int buf_ = (S) & 1;                                                            \
        _Pragma("unroll")                                                              \
        for (int i_ = 0; i_ < 8; i_++) {                                               \
            int idx_ = tid + i_ * 256;                                                 \
            int r_ = idx_ >> 5, c_ = idx_ & 31;                                        \
            cpa16(B_s + buf_ * (64 * WB_STRIDE) + r_ * WB_STRIDE + c_ * 8,             \
                  Wout + (size_t)((S) * 64 + r_) * EC + c_ * 8);                       \
        }                                                                              \
        cpa_commit();                                                                  \
    }

    WOUT_ISSUE(0);
    const int NCC = VC / 64;
    for (int nc = 0; nc < NCC; nc++) {
        cpa_wait<0>();
        __syncthreads();
        if (nc + 1 < NCC) WOUT_ISSUE(nc + 1);
        int buf = nc & 1;
        const bf16* b_base = B_s + buf * (64 * WB_STRIDE);

        wmma::fragment<wmma::accumulator, 16, 16, 16, float> acc[2];
        wmma::fill_fragment(acc[0], 0.0f);
        wmma::fill_fragment(acc[1], 0.0f);
#pragma unroll
        for (int kk = 0; kk < 16; kk++) {
            wmma::fragment<wmma::matrix_a, 16, 16, 16, bf16, wmma::row_major> af[2];
            wmma::fragment<wmma::matrix_b, 16, 16, 16, bf16, wmma::col_major> bfr;
            wmma::load_matrix_sync(af[0], A_s + (wm * 32) * WA_STRIDE + kk * 16, WA_STRIDE);
            wmma::load_matrix_sync(af[1], A_s + (wm * 32 + 16) * WA_STRIDE + kk * 16, WA_STRIDE);
            wmma::load_matrix_sync(bfr, b_base + (wn * 16) * WB_STRIDE + kk * 16, WB_STRIDE);
            wmma::mma_sync(acc[0], af[0], bfr, acc[0]);
            wmma::mma_sync(acc[1], af[1], bfr, acc[1]);
        }
        wmma::store_matrix_sync(C_s + (wm * 32) * 72 + wn * 16, acc[0], 72, wmma::mem_row_major);
        wmma::store_matrix_sync(C_s + (wm * 32 + 16) * 72 + wn * 16, acc[1], 72, wmma::mem_row_major);
        __syncthreads();

        {
            int n0v = nc * 64;
            int r = tid >> 2, q = tid & 3;
            int tgt = rTgt[r];
            float lv[16];
            float lm = -1e30f;
#pragma unroll
            for (int c = 0; c < 16; c++) {
                int col = q * 16 + c;
                int gcol = n0v + col;
                float l = C_s[r * 72 + col] + bout[gcol];
                lv[c] = l;
                lm = fmaxf(lm, l);
                if (gcol == 2) rE[r] = l;
                if (gcol == tgt) rT[r] = l;
            }
            float ls = 0.f;
#pragma unroll
            for (int c = 0; c < 16; c++) ls += __expf(lv[c] - lm);
#pragma unroll
            for (int off = 1; off < 4; off <<= 1) {
                float om = __shfl_xor_sync(0xffffffffu, lm, off);
                float os = __shfl_xor_sync(0xffffffffu, ls, off);
                float nm = fmaxf(lm, om);
                ls = ls * __expf(lm - nm) + os * __expf(om - nm);
                lm = nm;
            }
            if (q == 0) {
                float M = rM[r], S = rS[r];
                float nm = fmaxf(M, lm);
                rS[r] = S * __expf(M - nm) + ls * __expf(lm - nm);
                rM[r] = nm;
            }
        }
        __syncthreads();
    }

    if (tid < 64) {
        int n = m0 + tid;
        float lse = rM[tid] + logf(rS[tid]);
        int j = n % JC;
        bool valid = (j + kstep) <= T2C;
        float cv = cum[n];
        outp[(size_t)n * KSEG + kstep] = valid ? (cv + rE[tid] - lse) : -1e9f;
        cum[n] = cv + rT[tid] - lse;
    }
#undef WOUT_ISSUE
}

// ---------------- host launch ----------------
static inline float* fsym(const void* sym) {
    void* p = nullptr; cudaGetSymbolAddress(&p, sym); return (float*)p;
}
static inline bf16* bsym(const void* sym) {
    void* p = nullptr; cudaGetSymbolAddress(&p, sym); return (bf16*)p;
}
static inline int* isym(const void* sym) {
    void* p = nullptr; cudaGetSymbolAddress(&p, sym); return (int*)p;
}
static inline uint8_t* usym(const void* sym) {
    void* p = nullptr; cudaGetSymbolAddress(&p, sym); return (uint8_t*)p;
}

extern "C" void kernel_launch(void* const* d_in, const int* in_sizes, int n_in,
                              void* d_out, int out_size) {
    const int*   prev   = (const int*)d_in[0];
    const float* encO   = (const float*)d_in[1];
    const float* encH   = (const float*)d_in[2];
    const float* encC   = (const float*)d_in[3];
    const float* embed  = (const float*)d_in[4];
    const float* Wph    = (const float*)d_in[5];
    const float* bph    = (const float*)d_in[6];
    const float* Wpc    = (const float*)d_in[7];
    const float* bpc    = (const float*)d_in[8];
    const float* Wih0   = (const float*)d_in[9];
    const float* Whh0   = (const float*)d_in[10];
    const float* bih0   = (const float*)d_in[11];
    const float* bhh0   = (const float*)d_in[12];
    const float* Wih1   = (const float*)d_in[13];
    const float* Whh1   = (const float*)d_in[14];
    const float* bih1   = (const float*)d_in[15];
    const float* bhh1   = (const float*)d_in[16];
    const float* Wfc    = (const float*)d_in[17];
    const float* bfc    = (const float*)d_in[18];
    const float* Wout   = (const float*)d_in[19];
    const float* bout   = (const float*)d_in[20];
    float* outp = (float*)d_out;

    uint8_t* pX1f8 = usym(d_X1f8);
    bf16*  pX1b  = bsym(d_X1b);
    float* pc0   = fsym(d_c0);
    float* pc1   = fsym(d_c1);
    bf16*  pfco  = bsym(d_fco);
    float* pgin  = fsym(d_gin);
    float* pgctx = fsym(d_gctx);
    bf16*  pctxb = bsym(d_ctxb);
    float* pcum  = fsym(d_cum);
    float* pb0p  = fsym(d_b0p);
    float* pb1p  = fsym(d_b1p);
    int*   pgoff = isym(d_ginoff);
    int*   pcoff = isym(d_ctxoff);
    int*   ptgt  = isym(d_tgttok);
    uint8_t* pWhh0f8  = usym(d_Whh0f8);
    uint8_t* pW1catf8 = usym(d_W1catf8);
    bf16*  pWfcb   = bsym(d_Wfcb);
    bf16*  pWoutb  = bsym(d_Woutb);
    bf16*  pembb   = bsym(d_embb);
    bf16*  pWih0b  = bsym(d_Wih0b);
    bf16*  pWphb   = bsym(d_Wphb);
    bf16*  pencOb  = bsym(d_encOb);

    static bool s_init = false;
    static cudaStream_t sW;
    static cudaEvent_t evF[KSEG], evW[KSEG];
    if (!s_init) {
        cudaStreamCreateWithFlags(&sW, cudaStreamNonBlocking);
        for (int i = 0; i < KSEG; i++) {
            cudaEventCreateWithFlags(&evF[i], cudaEventDisableTiming);
            cudaEventCreateWithFlags(&evW[i], cudaEventDisableTiming);
        }
        s_init = true;
    }

    cudaFuncSetAttribute(gemm_bf<0, true,  false>, cudaFuncAttributeMaxDynamicSharedMemorySize, GSM_BYTES);
    cudaFuncSetAttribute(gemm_bf<1, true,  true >, cudaFuncAttributeMaxDynamicSharedMemorySize, GSM_BYTES);
    cudaFuncSetAttribute(gemm_bf<1, false, false>, cudaFuncAttributeMaxDynamicSharedMemorySize, GSM_BYTES);
    cudaFuncSetAttribute(gemm_bf<1, false, true >, cudaFuncAttributeMaxDynamicSharedMemorySize, GSM_BYTES);
    cudaFuncSetAttribute(gemm_f8<4>, cudaFuncAttributeMaxDynamicSharedMemorySize, F8_GSM);
    cudaFuncSetAttribute(gemm_f8<5>, cudaFuncAttributeMaxDynamicSharedMemorySize, F8_GSM);
    cudaFuncSetAttribute(wout_lse, cudaFuncAttributeMaxDynamicSharedMemorySize, WOUT_SMEM_BYTES);

    // ---- prologue ----
    wperm_f8_kernel<<<(GHC * HC + 255) / 256, 256>>>(Whh0, pWhh0f8, HC);
    w1catperm_f8_kernel<<<(GHC * 1024 + 255) / 256, 256>>>(Wih1, Whh1);
    wperm_kernel<<<(GHC * (EC + HC) + 255) / 256, 256>>>(Wih0, pWih0b, EC + HC);
    biasperm_kernel<<<(GHC + 255) / 256, 256>>>(bih0, bhh0, bih1, bhh1);
    cvt_kernel<<<(EC * HC / 4 + 255) / 256, 256>>>(Wfc, pWfcb, EC * HC / 4);
    cvt_kernel<<<(VC * EC / 4 + 255) / 256, 256>>>(Wout, pWoutb, VC * EC / 4);
    cvt_kernel<<<((VC + 2) * EC / 4 + 255) / 256, 256>>>(embed, pembb, (VC + 2) * EC / 4);
    cvt_kernel<<<(HC * UC / 4 + 255) / 256, 256>>>(Wph, pWphb, HC * UC / 4);
    cvt_kernel<<<(T1C * BB * UC / 4 + 255) / 256, 256>>>(encO, pencOb, T1C * BB * UC / 4);

    tok_kernel<<<(GIN_ROWS_PAD + 255) / 256, 256>>>(prev);
    ctxoff_kernel<<<1, 256>>>();
    hcinit_kernel<<<(2 * BB * HC + 255) / 256, 256>>>(encH, encC, Wph, bph, Wpc, bpc);
    initX_kernel<<<(NN * HC) / 256, 256>>>();

    // ctx(bf16) = encO @ Wph^T + bph : M=256, N=512, K=1024 (gather A)
    gemm_bf<1, true, true><<<dim3(512 / 128, 256 / 128), 256, GSM_BYTES>>>(
        pencOb, 0, pWphb, UC, pctxb, HC, UC, pcoff, bph);
    // gctx = ctx @ Wih0p[:,E:]^T + b0p : M=256, N=2048(perm), K=512
    gemm_bf<1, false, false><<<dim3(GHC / 128, 256 / 128), 256, GSM_BYTES>>>(
        pctxb, HC, pWih0b + EC, EC + HC, pgctx, GHC, HC, nullptr, pb0p);
    // gin = emb @ Wih0p[:, :E]^T : M=2432, N=2048(perm), K=256 (gather A)
    gemm_bf<0, true, false><<<dim3(GHC / 128, GIN_ROWS_PAD / 128), 256, GSM_BYTES>>>(
        pembb, 0, pWih0b, EC + HC, pgin, GHC, EC, pgoff, nullptr);

    for (int k = 0; k < KSEG; k++) {
        bf16* fcobuf = pfco + (size_t)(k & 1) * NN * EC;
        // layer 0 (fp8): fused cell -> c0, h0(f8)
        gemm_f8<4><<<dim3(GHC / 128, NN / 128), 256, F8_GSM>>>(
            pX1f8, 1024, pWhh0f8, HC, HC, pgin, pgctx, k, pc0, pX1f8, nullptr);
        // layer 1 (fp8): fused cell -> c1, h1(f8 + bf16)
        gemm_f8<5><<<dim3(GHC / 128, NN / 128), 256, F8_GSM>>>(
            pX1f8, 1024, pW1catf8, 1024, 1024, pb1p, nullptr, k, pc1, pX1f8 + 512, pX1b);
        if (k >= 2) cudaStreamWaitEvent(0, evW[k - 2], 0);
        // fco(bf16) = h1 @ Wfc^T + bfc
        gemm_bf<1, false, true><<<dim3(EC / 128, NN / 128), 256, GSM_BYTES>>>(
            pX1b, HC, pWfcb, HC, fcobuf, EC, HC, nullptr, bfc);
        cudaEventRecord(evF[k], 0);
        cudaStreamWaitEvent(sW, evF[k], 0);
        wout_lse<<<NN / 64, 256, WOUT_SMEM_BYTES, sW>>>(fcobuf, pWoutb, bout, ptgt, pcum, outp, k);
        cudaEventRecord(evW[k], sW);
    }
    cudaStreamWaitEvent(0, evW[KSEG - 1], 0);
}

// round 10
// speedup vs baseline: 1.2656x; 1.2656x over previous
#include <cuda_runtime.h>
#include <cuda_bf16.h>
#include <mma.h>
#include <math.h>
#include <stdint.h>

using namespace nvcuda;

// ---------------- problem constants ----------------
#define BB 8
#define T1C 32
#define T2C 32
#define JC 33
#define KSEG 9
#define NN 8448
#define EC 256
#define HC 512
#define UC 1024
#define GHC 2048
#define VC 8000
#define START_ID 8001
#define GIN_ROWS 2376
#define GIN_ROWS_PAD 2432

typedef __nv_bfloat16 bf16;
typedef __nv_bfloat162 bf162;

// ---------------- device scratch ----------------
__device__ bf16  d_X1[NN * 1024];
__device__ float d_c0[NN * HC];
__device__ float d_c1[NN * HC];
__device__ bf16  d_fco[2 * NN * EC];          // double-buffered across steps
__device__ float d_gin[GIN_ROWS_PAD * GHC];
__device__ float d_gctx[256 * GHC];
__device__ bf16  d_ctxb[256 * HC];
__device__ float d_hinit[2 * BB * HC];
__device__ float d_cinit[2 * BB * HC];
__device__ float d_cum[NN];
__device__ float d_b0p[GHC];
__device__ float d_b1p[GHC];
__device__ int   d_ginoff[GIN_ROWS_PAD];
__device__ int   d_ctxoff[256];
__device__ int   d_tgttok[GIN_ROWS];
__device__ bf16 d_Whh0b[GHC * HC];
__device__ bf16 d_W1catb[GHC * 1024];
__device__ bf16 d_Wfcb[EC * HC];
__device__ bf16 d_Woutb[VC * EC];
__device__ bf16 d_embb[(VC + 2) * EC];
__device__ bf16 d_Wih0b[GHC * (EC + HC)];
__device__ bf16 d_Wphb[HC * UC];
__device__ bf16 d_encOb[T1C * BB * UC];

__device__ __forceinline__ float tanha(float x) {
    float y; asm("tanh.approx.f32 %0, %1;" : "=f"(y) : "f"(x)); return y;
}
__device__ __forceinline__ float sigfast(float x) { return 0.5f * tanha(0.5f * x) + 0.5f; }

__device__ __forceinline__ void cpa16(void* dst, const void* src) {
    uint32_t d = (uint32_t)__cvta_generic_to_shared(dst);
    asm volatile("cp.async.cg.shared.global [%0], [%1], 16;\n" :: "r"(d), "l"(src));
}
__device__ __forceinline__ void cpa_commit() { asm volatile("cp.async.commit_group;\n"); }
template <int N> __device__ __forceinline__ void cpa_wait() {
    asm volatile("cp.async.wait_group %0;\n" :: "n"(N));
}

// ---------------- prologue kernels ----------------
__global__ void cvt_kernel(const float* __restrict__ src, bf16* __restrict__ dst, int n4) {
    int i = blockIdx.x * blockDim.x + threadIdx.x;
    if (i >= n4) return;
    float4 v = ((const float4*)src)[i];
    bf162* d = (bf162*)dst + i * 2;
    d[0] = __floats2bfloat162_rn(v.x, v.y);
    d[1] = __floats2bfloat162_rn(v.z, v.w);
}

__global__ void wperm_kernel(const float* __restrict__ W, bf16* __restrict__ dst, int ldw) {
    int idx = blockIdx.x * blockDim.x + threadIdx.x;
    if (idx >= GHC * ldw) return;
    int np = idx / ldw, c = idx - np * ldw;
    int h = np >> 2, gate = np & 3;
    dst[idx] = __float2bfloat16(W[(size_t)(gate * HC + h) * ldw + c]);
}

__global__ void w1catperm_kernel(const float* __restrict__ Wih1, const float* __restrict__ Whh1) {
    int idx = blockIdx.x * blockDim.x + threadIdx.x;
    if (idx >= GHC * 1024) return;
    int np = idx >> 10, c = idx & 1023;
    int o = (np & 3) * HC + (np >> 2);
    float v = (c < HC) ? Wih1[(size_t)o * HC + c] : Whh1[(size_t)o * HC + (c - HC)];
    d_W1catb[idx] = __float2bfloat16(v);
}

__global__ void biasperm_kernel(const float* __restrict__ bih0, const float* __restrict__ bhh0,
                                const float* __restrict__ bih1, const float* __restrict__ bhh1) {
    int idx = blockIdx.x * blockDim.x + threadIdx.x;
    if (idx >= GHC) return;
    int o = (idx & 3) * HC + (idx >> 2);
    d_b0p[idx] = bih0[o] + bhh0[o];
    d_b1p[idx] = bih1[o] + bhh1[o];
}

__global__ void tok_kernel(const int* __restrict__ prev) {
    int r = blockIdx.x * blockDim.x + threadIdx.x;
    if (r >= GIN_ROWS_PAD) return;
    if (r < GIN_ROWS) {
        int k = r / (BB * JC);
        int bj = r - k * (BB * JC);
        int b = bj / JC;
        int j = bj - b * JC;
        int pin = j + k - 1; if (pin > T2C - 1) pin = T2C - 1;
        int tin = (k == 0) ? START_ID : prev[b * T2C + pin];
        d_ginoff[r] = tin * EC;
        int pt = j + k; if (pt > T2C - 1) pt = T2C - 1;
        d_tgttok[r] = prev[b * T2C + pt];
    } else {
        d_ginoff[r] = 0;
    }
}

__global__ void ctxoff_kernel() {
    int r = threadIdx.x;
    if (r < 256) {
        int b = r / T1C, t1 = r - b * T1C;
        d_ctxoff[r] = t1 * (BB * UC) + b * UC;
    }
}

__global__ void hcinit_kernel(const float* __restrict__ ench, const float* __restrict__ encc,
                              const float* __restrict__ Wph, const float* __restrict__ bph,
                              const float* __restrict__ Wpc, const float* __restrict__ bpc) {
    int idx = blockIdx.x * blockDim.x + threadIdx.x;
    if (idx >= 2 * BB * HC) return;
    int l = idx / (BB * HC);
    int b = (idx / HC) % BB;
    int h = idx % HC;
    const float4* eh = (const float4*)(ench + l * BB * UC + b * UC);
    const float4* ec = (const float4*)(encc + l * BB * UC + b * UC);
    const float4* wh = (const float4*)(Wph + (size_t)h * UC);
    const float4* wc = (const float4*)(Wpc + (size_t)h * UC);
    float sh = 0.f, sc = 0.f;
    for (int u = 0; u < UC / 4; u++) {
        float4 a = eh[u], w = wh[u];
        sh += a.x * w.x + a.y * w.y + a.z * w.z + a.w * w.w;
        float4 a2 = ec[u], w2 = wc[u];
        sc += a2.x * w2.x + a2.y * w2.y + a2.z * w2.z + a2.w * w2.w;
    }
    d_hinit[idx] = sh + bph[h];
    d_cinit[idx] = sc + bpc[h];
}

__global__ void initX_kernel() {
    int idx = blockIdx.x * blockDim.x + threadIdx.x;
    if (idx >= NN * HC) return;
    int n = idx >> 9, h = idx & 511;
    int b = n / (T1C * JC);
    d_X1[(size_t)n * 1024 + h]       = __float2bfloat16(d_hinit[b * HC + h]);
    d_X1[(size_t)n * 1024 + 512 + h] = __float2bfloat16(d_hinit[BB * HC + b * HC + h]);
    d_c0[idx] = d_cinit[b * HC + h];
    d_c1[idx] = d_cinit[BB * HC + b * HC + h];
    if (h == 0) d_cum[n] = 0.f;
}

// ---------------- bf16 TN GEMM, 128x128 tiles, single-sync 2-stage pipeline (R3/R7 config) ----
// EPI: 0 none, 1 +e1[n], 4 CELL0 (+gin+gctx, cell), 5 CELL1 (+e1[n], cell)
#define SASTRIDE 40
#define GSM_BYTES 67584
template <int EPI, bool GATHER, bool OBF>
__launch_bounds__(256)
__global__ void gemm_bf(const bf16* __restrict__ A, int lda,
                        const bf16* __restrict__ Bm, int ldb,
                        void* __restrict__ Cv, int ldc, int K,
                        const int* __restrict__ rowoff,
                        const float* __restrict__ e1, const float* __restrict__ e2,
                        int kstep, float* __restrict__ cptr, bf16* __restrict__ hout) {
    extern __shared__ char smraw[];
    bf16* sA = (bf16*)smraw;
    bf16* sB = sA + 2 * 128 * SASTRIDE;
    float* sC = (float*)smraw;

    int tid = threadIdx.x;
    int m0 = blockIdx.y * 128, n0 = blockIdx.x * 128;
    int wid = tid >> 5;
    int wm = wid & 1, wn = wid >> 1;

    wmma::fragment<wmma::accumulator, 16, 16, 16, float> acc[4][2];
#pragma unroll
    for (int mi = 0; mi < 4; mi++)
#pragma unroll
        for (int ni = 0; ni < 2; ni++) wmma::fill_fragment(acc[mi][ni], 0.0f);

    int nk = K >> 5;

#define GEMM_ISSUE(S)                                                                    \
    {                                                                                    \
        int buf_ = (S) & 1;                                                              \
        int k0_ = (S) << 5;                                                              \
        _Pragma("unroll")                                                                \
        for (int i_ = 0; i_ < 2; i_++) {                                                 \
            int idx_ = tid + i_ * 256;                                                   \
            int r_ = idx_ >> 2, c_ = idx_ & 3;                                           \
            const bf16* src_ = GATHER ? (A + rowoff[m0 + r_] + k0_ + c_ * 8)             \
                                      : (A + (size_t)(m0 + r_) * lda + k0_ + c_ * 8);    \
            cpa16(sA + buf_ * (128 * SASTRIDE) + r_ * SASTRIDE + c_ * 8, src_);          \
        }                                                                                \
        _Pragma("unroll")                                                                \
        for (int i_ = 0; i_ < 2; i_++) {                                                 \
            int idx_ = tid + i_ * 256;                                                   \
            int r_ = idx_ >> 2, c_ = idx_ & 3;                                           \
            cpa16(sB + buf_ * (128 * SASTRIDE) + r_ * SASTRIDE + c_ * 8,                 \
                  Bm + (size_t)(n0 + r_) * ldb + k0_ + c_ * 8);                          \
        }                                                                                \
        cpa_commit();                                                                    \
    }

    GEMM_ISSUE(0);
    for (int s = 0; s < nk; s++) {
        cpa_wait<0>();
        __syncthreads();
        if (s + 1 < nk) GEMM_ISSUE(s + 1);
        int buf = s & 1;
        const bf16* a_base = sA + buf * (128 * SASTRIDE);
        const bf16* b_base = sB + buf * (128 * SASTRIDE);
#pragma unroll
        for (int kk = 0; kk < 2; kk++) {
            wmma::fragment<wmma::matrix_a, 16, 16, 16, bf16, wmma::row_major> af[4];
            wmma::fragment<wmma::matrix_b, 16, 16, 16, bf16, wmma::col_major> bfr[2];
#pragma unroll
            for (int mi = 0; mi < 4; mi++)
                wmma::load_matrix_sync(af[mi], a_base + (wm * 64 + mi * 16) * SASTRIDE + kk * 16, SASTRIDE);
#pragma unroll
            for (int ni = 0; ni < 2; ni++)
                wmma::load_matrix_sync(bfr[ni], b_base + (wn * 32 + ni * 16) * SASTRIDE + kk * 16, SASTRIDE);
#pragma unroll
            for (int mi = 0; mi < 4; mi++)
#pragma unroll
                for (int ni = 0; ni < 2; ni++)
                    wmma::mma_sync(acc[mi][ni], af[mi], bfr[ni], acc[mi][ni]);
        }
    }
    __syncthreads();
#pragma unroll
    for (int mi = 0; mi < 4; mi++)
#pragma unroll
        for (int ni = 0; ni < 2; ni++)
            wmma::store_matrix_sync(sC + (wm * 64 + mi * 16) * 132 + wn * 32 + ni * 16,
                                    acc[mi][ni], 132, wmma::mem_row_major);
    __syncthreads();

#pragma unroll
    for (int i = 0; i < 16; i++) {
        int idx = tid + i * 256;
        int r = idx >> 5, c4 = idx & 31;
        float4 v = *(float4*)(sC + r * 132 + c4 * 4);
        int m = m0 + r;
        int nb = n0 + c4 * 4;
        if (EPI == 1 || EPI == 5) {
            float4 bb = *(const float4*)(e1 + nb);
            v.x += bb.x; v.y += bb.y; v.z += bb.z; v.w += bb.w;
        }
        if (EPI == 4) {
            int b = m / (T1C * JC);
            int rem = m - b * (T1C * JC);
            int t1 = rem / JC;
            int j = rem - t1 * JC;
            const float* gi = e1 + (size_t)((kstep * BB + b) * JC + j) * GHC + nb;
            const float* gc = e2 + (size_t)(b * T1C + t1) * GHC + nb;
            float4 a1 = *(const float4*)gi;
            float4 a2 = *(const float4*)gc;
            v.x += a1.x + a2.x; v.y += a1.y + a2.y; v.z += a1.z + a2.z; v.w += a1.w + a2.w;
        }
        if (EPI == 4 || EPI == 5) {
            int h = nb >> 2;
            size_t cix = (size_t)m * HC + h;
            float cold = cptr[cix];
            float cn = sigfast(v.y) * cold + sigfast(v.x) * tanha(v.z);
            cptr[cix] = cn;
            hout[(size_t)m * 1024 + h] = __float2bfloat16(sigfast(v.w) * tanha(cn));
        } else if (OBF) {
            bf162* p = (bf162*)((bf16*)Cv + (size_t)m * ldc + nb);
            p[0] = __floats2bfloat162_rn(v.x, v.y);
            p[1] = __floats2bfloat162_rn(v.z, v.w);
        } else {
            *(float4*)((float*)Cv + (size_t)m * ldc + nb) = v;
        }
    }
#undef GEMM_ISSUE
}

// ---------------- fused Wout GEMM + online logsumexp -------------------------------
// 128-col vocab chunks (63 iters, tail masked), 32x32 warp tiles (1:1 LDSM:HMMA),
// online branchy LSE scan — no lv[] scratch array, low register pressure.
#define WA_STRIDE 264
#define WB_STRIDE 264
#define WC_STRIDE 136
#define WOUT_SMEM_BYTES (64 * WA_STRIDE * 2 + 2 * 128 * WB_STRIDE * 2 + 64 * WC_STRIDE * 4 + 64 * 5 * 4)
__launch_bounds__(256)
__global__ void wout_lse(const bf16* __restrict__ fco, const bf16* __restrict__ Wout,
                         const float* __restrict__ bout, const int* __restrict__ tgttok,
                         float* __restrict__ cum, float* __restrict__ outp, int kstep) {
    extern __shared__ char smraw[];
    bf16* A_s = (bf16*)smraw;                          // 64 x 264
    bf16* B_s = A_s + 64 * WA_STRIDE;                  // 2 x 128 x 264
    float* C_s = (float*)(B_s + 2 * 128 * WB_STRIDE);  // 64 x 136
    float* rM = C_s + 64 * WC_STRIDE;
    float* rS = rM + 64;
    float* rE = rS + 64;
    float* rT = rE + 64;
    int* rTgt = (int*)(rT + 64);

    int tid = threadIdx.x;
    int m0 = blockIdx.x * 64;

#pragma unroll
    for (int i = 0; i < 8; i++) {      // A: 64 x 256 bf16
        int idx = tid + i * 256;
        int r = idx >> 5, c = idx & 31;
        *(uint4*)(A_s + r * WA_STRIDE + c * 8) = *(const uint4*)(fco + (size_t)(m0 + r) * EC + c * 8);
    }
    if (tid < 64) {
        int n = m0 + tid;
        int b = n / (T1C * JC);
        int rem = n - b * (T1C * JC);
        int j = rem % JC;
        rTgt[tid] = tgttok[(kstep * BB + b) * JC + j];
        rM[tid] = -1e30f; rS[tid] = 0.f; rE[tid] = 0.f; rT[tid] = 0.f;
    }

    int wid = tid >> 5;
    int wm = wid & 1, wn = wid >> 1;   // 2m x 4n; warp tile 32 x 32

#define WOUT_ISSUE(S)                                                                  \
    {                                                                                  \
        int buf_ = (S) & 1;                                                            \
        _Pragma("unroll")                                                              \
        for (int i_ = 0; i_ < 16; i_++) {                                              \
            int idx_ = tid + i_ * 256;                                                 \
            int r_ = idx_ >> 5, c_ = idx_ & 31;                                        \
            int vr_ = (S) * 128 + r_; if (vr_ > VC - 1) vr_ = VC - 1;                  \
            cpa16(B_s + buf_ * (128 * WB_STRIDE) + r_ * WB_STRIDE + c_ * 8,            \
                  Wout + (size_t)vr_ * EC + c_ * 8);                                   \
        }                                                                              \
        cpa_commit();                                                                  \
    }

    WOUT_ISSUE(0);
    const int NCC = 63;                // ceil(8000/128)
    for (int nc = 0; nc < NCC; nc++) {
        cpa_wait<0>();
        __syncthreads();
        if (nc + 1 < NCC) WOUT_ISSUE(nc + 1);
        int buf = nc & 1;
        const bf16* b_base = B_s + buf * (128 * WB_STRIDE);

        wmma::fragment<wmma::accumulator, 16, 16, 16, float> acc[2][2];
#pragma unroll
        for (int mi = 0; mi < 2; mi++)
#pragma unroll
            for (int ni = 0; ni < 2; ni++) wmma::fill_fragment(acc[mi][ni], 0.0f);
#pragma unroll
        for (int kk = 0; kk < 16; kk++) {
            wmma::fragment<wmma::matrix_a, 16, 16, 16, bf16, wmma::row_major> af[2];
            wmma::fragment<wmma::matrix_b, 16, 16, 16, bf16, wmma::col_major> bfr[2];
#pragma unroll
            for (int mi = 0; mi < 2; mi++)
                wmma::load_matrix_sync(af[mi], A_s + (wm * 32 + mi * 16) * WA_STRIDE + kk * 16, WA_STRIDE);
#pragma unroll
            for (int ni = 0; ni < 2; ni++)
                wmma::load_matrix_sync(bfr[ni], b_base + (wn * 32 + ni * 16) * WB_STRIDE + kk * 16, WB_STRIDE);
#pragma unroll
            for (int mi = 0; mi < 2; mi++)
#pragma unroll
                for (int ni = 0; ni < 2; ni++)
                    wmma::mma_sync(acc[mi][ni], af[mi], bfr[ni], acc[mi][ni]);
        }
#pragma unroll
        for (int mi = 0; mi < 2; mi++)
#pragma unroll
            for (int ni = 0; ni < 2; ni++)
                wmma::store_matrix_sync(C_s + (wm * 32 + mi * 16) * WC_STRIDE + wn * 32 + ni * 16,
                                        acc[mi][ni], WC_STRIDE, wmma::mem_row_major);
        __syncthreads();

        {   // online LSE over this 128-col chunk: 4 lanes per row, 32 cols each
            int n0v = nc * 128;
            int r = tid >> 2, q = tid & 3;
            int tgt = rTgt[r];
            float lm = -1e30f, ls = 0.f;
#pragma unroll
            for (int c = 0; c < 32; c++) {
                int col = q * 32 + c;
                int gcol = n0v + col;
                if (gcol < VC) {
                    float l = C_s[r * WC_STRIDE + col] + bout[gcol];
                    if (gcol == 2) rE[r] = l;
                    if (gcol == tgt) rT[r] = l;
                    if (l <= lm) {
                        ls += __expf(l - lm);
                    } else {
                        ls = ls * __expf(lm - l) + 1.0f;
                        lm = l;
                    }
                }
            }
#pragma unroll
            for (int off = 1; off < 4; off <<= 1) {
                float om = __shfl_xor_sync(0xffffffffu, lm, off);
                float os = __shfl_xor_sync(0xffffffffu, ls, off);
                float nm = fmaxf(lm, om);
                ls = ls * __expf(lm - nm) + os * __expf(om - nm);
                lm = nm;
            }
            if (q == 0) {
                float M = rM[r], S = rS[r];
                float nm = fmaxf(M, lm);
                rS[r] = S * __expf(M - nm) + ls * __expf(lm - nm);
                rM[r] = nm;
            }
        }
        __syncthreads();
    }

    if (tid < 64) {
        int n = m0 + tid;
        float lse = rM[tid] + logf(rS[tid]);
        int j = n % JC;
        bool valid = (j + kstep) <= T2C;
        float cv = cum[n];
        outp[(size_t)n * KSEG + kstep] = valid ? (cv + rE[tid] - lse) : -1e9f;
        cum[n] = cv + rT[tid] - lse;
    }
#undef WOUT_ISSUE
}

// ---------------- host launch ----------------
static inline float* fsym(const void* sym) {
    void* p = nullptr; cudaGetSymbolAddress(&p, sym); return (float*)p;
}
static inline bf16* bsym(const void* sym) {
    void* p = nullptr; cudaGetSymbolAddress(&p, sym); return (bf16*)p;
}
static inline int* isym(const void* sym) {
    void* p = nullptr; cudaGetSymbolAddress(&p, sym); return (int*)p;
}

extern "C" void kernel_launch(void* const* d_in, const int* in_sizes, int n_in,
                              void* d_out, int out_size) {
    const int*   prev   = (const int*)d_in[0];
    const float* encO   = (const float*)d_in[1];
    const float* encH   = (const float*)d_in[2];
    const float* encC   = (const float*)d_in[3];
    const float* embed  = (const float*)d_in[4];
    const float* Wph    = (const float*)d_in[5];
    const float* bph    = (const float*)d_in[6];
    const float* Wpc    = (const float*)d_in[7];
    const float* bpc    = (const float*)d_in[8];
    const float* Wih0   = (const float*)d_in[9];
    const float* Whh0   = (const float*)d_in[10];
    const float* bih0   = (const float*)d_in[11];
    const float* bhh0   = (const float*)d_in[12];
    const float* Wih1   = (const float*)d_in[13];
    const float* Whh1   = (const float*)d_in[14];
    const float* bih1   = (const float*)d_in[15];
    const float* bhh1   = (const float*)d_in[16];
    const float* Wfc    = (const float*)d_in[17];
    const float* bfc    = (const float*)d_in[18];
    const float* Wout   = (const float*)d_in[19];
    const float* bout   = (const float*)d_in[20];
    float* outp = (float*)d_out;

    bf16*  pX1   = bsym(d_X1);
    float* pc0   = fsym(d_c0);
    float* pc1   = fsym(d_c1);
    bf16*  pfco  = bsym(d_fco);
    float* pgin  = fsym(d_gin);
    float* pgctx = fsym(d_gctx);
    bf16*  pctxb = bsym(d_ctxb);
    float* pcum  = fsym(d_cum);
    float* pb0p  = fsym(d_b0p);
    float* pb1p  = fsym(d_b1p);
    int*   pgoff = isym(d_ginoff);
    int*   pcoff = isym(d_ctxoff);
    int*   ptgt  = isym(d_tgttok);
    bf16*  pWhh0b  = bsym(d_Whh0b);
    bf16*  pW1catb = bsym(d_W1catb);
    bf16*  pWfcb   = bsym(d_Wfcb);
    bf16*  pWoutb  = bsym(d_Woutb);
    bf16*  pembb   = bsym(d_embb);
    bf16*  pWih0b  = bsym(d_Wih0b);
    bf16*  pWphb   = bsym(d_Wphb);
    bf16*  pencOb  = bsym(d_encOb);

    // one-time stream/event setup (topology identical every capture)
    static bool s_init = false;
    static cudaStream_t sW;
    static cudaEvent_t evF[KSEG], evW[KSEG];
    if (!s_init) {
        cudaStreamCreateWithFlags(&sW, cudaStreamNonBlocking);
        for (int i = 0; i < KSEG; i++) {
            cudaEventCreateWithFlags(&evF[i], cudaEventDisableTiming);
            cudaEventCreateWithFlags(&evW[i], cudaEventDisableTiming);
        }
        s_init = true;
    }

    cudaFuncSetAttribute(gemm_bf<0, true,  false>, cudaFuncAttributeMaxDynamicSharedMemorySize, GSM_BYTES);
    cudaFuncSetAttribute(gemm_bf<1, true,  true >, cudaFuncAttributeMaxDynamicSharedMemorySize, GSM_BYTES);
    cudaFuncSetAttribute(gemm_bf<1, false, false>, cudaFuncAttributeMaxDynamicSharedMemorySize, GSM_BYTES);
    cudaFuncSetAttribute(gemm_bf<1, false, true >, cudaFuncAttributeMaxDynamicSharedMemorySize, GSM_BYTES);
    cudaFuncSetAttribute(gemm_bf<4, false, false>, cudaFuncAttributeMaxDynamicSharedMemorySize, GSM_BYTES);
    cudaFuncSetAttribute(gemm_bf<5, false, false>, cudaFuncAttributeMaxDynamicSharedMemorySize, GSM_BYTES);
    cudaFuncSetAttribute(wout_lse, cudaFuncAttributeMaxDynamicSharedMemorySize, WOUT_SMEM_BYTES);

    // ---- prologue: conversions / permutations ----
    wperm_kernel<<<(GHC * HC + 255) / 256, 256>>>(Whh0, pWhh0b, HC);
    w1catperm_kernel<<<(GHC * 1024 + 255) / 256, 256>>>(Wih1, Whh1);
    wperm_kernel<<<(GHC * (EC + HC) + 255) / 256, 256>>>(Wih0, pWih0b, EC + HC);
    biasperm_kernel<<<(GHC + 255) / 256, 256>>>(bih0, bhh0, bih1, bhh1);
    cvt_kernel<<<(EC * HC / 4 + 255) / 256, 256>>>(Wfc, pWfcb, EC * HC / 4);
    cvt_kernel<<<(VC * EC / 4 + 255) / 256, 256>>>(Wout, pWoutb, VC * EC / 4);
    cvt_kernel<<<((VC + 2) * EC / 4 + 255) / 256, 256>>>(embed, pembb, (VC + 2) * EC / 4);
    cvt_kernel<<<(HC * UC / 4 + 255) / 256, 256>>>(Wph, pWphb, HC * UC / 4);
    cvt_kernel<<<(T1C * BB * UC / 4 + 255) / 256, 256>>>(encO, pencOb, T1C * BB * UC / 4);

    tok_kernel<<<(GIN_ROWS_PAD + 255) / 256, 256>>>(prev);
    ctxoff_kernel<<<1, 256>>>();
    hcinit_kernel<<<(2 * BB * HC + 255) / 256, 256>>>(encH, encC, Wph, bph, Wpc, bpc);
    initX_kernel<<<(NN * HC) / 256, 256>>>();

    // ctx(bf16) = encO @ Wph^T + bph : M=256, N=512, K=1024 (gather A)
    gemm_bf<1, true, true><<<dim3(512 / 128, 256 / 128), 256, GSM_BYTES>>>(
        pencOb, 0, pWphb, UC, pctxb, HC, UC, pcoff, bph, nullptr, 0, nullptr, nullptr);
    // gctx = ctx @ Wih0p[:,E:]^T + b0p : M=256, N=2048(perm), K=512
    gemm_bf<1, false, false><<<dim3(GHC / 128, 256 / 128), 256, GSM_BYTES>>>(
        pctxb, HC, pWih0b + EC, EC + HC, pgctx, GHC, HC, nullptr, pb0p, nullptr, 0, nullptr, nullptr);
    // gin = emb @ Wih0p[:, :E]^T : M=2432, N=2048(perm), K=256 (gather A)
    gemm_bf<0, true, false><<<dim3(GHC / 128, GIN_ROWS_PAD / 128), 256, GSM_BYTES>>>(
        pembb, 0, pWih0b, EC + HC, pgin, GHC, EC, pgoff, nullptr, nullptr, 0, nullptr, nullptr);

    for (int k = 0; k < KSEG; k++) {
        bf16* fcobuf = pfco + (size_t)(k & 1) * NN * EC;
        // layer 0: g0 = h0 @ Whh0p^T + gin + gctx, fused cell -> c0, h0
        gemm_bf<4, false, false><<<dim3(GHC / 128, NN / 128), 256, GSM_BYTES>>>(
            pX1, 1024, pWhh0b, HC, nullptr, 0, HC, nullptr, pgin, pgctx, k, pc0, pX1);
        // layer 1: g1 = [h0|h1] @ W1catp^T + b1p, fused cell -> c1, h1
        gemm_bf<5, false, false><<<dim3(GHC / 128, NN / 128), 256, GSM_BYTES>>>(
            pX1, 1024, pW1catb, 1024, nullptr, 0, 1024, nullptr, pb1p, nullptr, k, pc1, pX1 + 512);
        // before fc(k) rewrites fco buffer (k&1), ensure wout(k-2) has drained it
        if (k >= 2) cudaStreamWaitEvent(0, evW[k - 2], 0);
        // fco(bf16) = h1 @ Wfc^T + bfc
        gemm_bf<1, false, true><<<dim3(EC / 128, NN / 128), 256, GSM_BYTES>>>(
            pX1 + 512, 1024, pWfcb, HC, fcobuf, EC, HC, nullptr, bfc, nullptr, 0, nullptr, nullptr);
        cudaEventRecord(evF[k], 0);
        // wout(k) runs on side stream, overlapping with step k+1's LSTM chain
        cudaStreamWaitEvent(sW, evF[k], 0);
        wout_lse<<<NN / 64, 256, WOUT_SMEM_BYTES, sW>>>(fcobuf, pWoutb, bout, ptgt, pcum, outp, k);
        cudaEventRecord(evW[k], sW);
    }
    // graph sink must depend on the last wout
    cudaStreamWaitEvent(0, evW[KSEG - 1], 0);
}

// round 11
// speedup vs baseline: 1.4096x; 1.1138x over previous
#include <cuda_runtime.h>
#include <cuda_bf16.h>
#include <mma.h>
#include <math.h>
#include <stdint.h>

using namespace nvcuda;

// ---------------- problem constants ----------------
#define BB 8
#define T1C 32
#define T2C 32
#define JC 33
#define KSEG 9
#define NN 8448
#define EC 256
#define HC 512
#define UC 1024
#define GHC 2048
#define VC 8000
#define START_ID 8001
#define GIN_ROWS 2376
#define GIN_ROWS_PAD 2432

typedef __nv_bfloat16 bf16;
typedef __nv_bfloat162 bf162;

// ---------------- device scratch ----------------
__device__ bf16  d_X1[NN * 1024];
__device__ float d_c0[NN * HC];
__device__ float d_c1[NN * HC];
__device__ bf16  d_fco[2 * NN * EC];          // double-buffered across steps
__device__ float d_gin[GIN_ROWS_PAD * GHC];
__device__ float d_gctx[256 * GHC];
__device__ bf16  d_ctxb[256 * HC];
__device__ float d_hinit[2 * BB * HC];
__device__ float d_cinit[2 * BB * HC];
__device__ float d_cum[NN];
__device__ float d_b0p[GHC];
__device__ float d_b1p[GHC];
__device__ int   d_ginoff[GIN_ROWS_PAD];
__device__ int   d_ctxoff[256];
__device__ int   d_tgttok[GIN_ROWS];
__device__ bf16 d_Whh0b[GHC * HC];
__device__ bf16 d_W1catb[GHC * 1024];
__device__ bf16 d_Wfcb[EC * HC];
__device__ bf16 d_Woutb[VC * EC];
__device__ bf16 d_embb[(VC + 2) * EC];
__device__ bf16 d_Wih0b[GHC * (EC + HC)];
__device__ bf16 d_Wphb[HC * UC];
__device__ bf16 d_encOb[T1C * BB * UC];

__device__ __forceinline__ float tanha(float x) {
    float y; asm("tanh.approx.f32 %0, %1;" : "=f"(y) : "f"(x)); return y;
}
__device__ __forceinline__ float sigfast(float x) { return 0.5f * tanha(0.5f * x) + 0.5f; }

__device__ __forceinline__ void cpa16(void* dst, const void* src) {
    uint32_t d = (uint32_t)__cvta_generic_to_shared(dst);
    asm volatile("cp.async.cg.shared.global [%0], [%1], 16;\n" :: "r"(d), "l"(src));
}
__device__ __forceinline__ void cpa_commit() { asm volatile("cp.async.commit_group;\n"); }
template <int N> __device__ __forceinline__ void cpa_wait() {
    asm volatile("cp.async.wait_group %0;\n" :: "n"(N));
}

// ---------------- prologue kernels ----------------
__global__ void cvt_kernel(const float* __restrict__ src, bf16* __restrict__ dst, int n4) {
    int i = blockIdx.x * blockDim.x + threadIdx.x;
    if (i >= n4) return;
    float4 v = ((const float4*)src)[i];
    bf162* d = (bf162*)dst + i * 2;
    d[0] = __floats2bfloat162_rn(v.x, v.y);
    d[1] = __floats2bfloat162_rn(v.z, v.w);
}

__global__ void wperm_kernel(const float* __restrict__ W, bf16* __restrict__ dst, int ldw) {
    int idx = blockIdx.x * blockDim.x + threadIdx.x;
    if (idx >= GHC * ldw) return;
    int np = idx / ldw, c = idx - np * ldw;
    int h = np >> 2, gate = np & 3;
    dst[idx] = __float2bfloat16(W[(size_t)(gate * HC + h) * ldw + c]);
}

__global__ void w1catperm_kernel(const float* __restrict__ Wih1, const float* __restrict__ Whh1) {
    int idx = blockIdx.x * blockDim.x + threadIdx.x;
    if (idx >= GHC * 1024) return;
    int np = idx >> 10, c = idx & 1023;
    int o = (np & 3) * HC + (np >> 2);
    float v = (c < HC) ? Wih1[(size_t)o * HC + c] : Whh1[(size_t)o * HC + (c - HC)];
    d_W1catb[idx] = __float2bfloat16(v);
}

__global__ void biasperm_kernel(const float* __restrict__ bih0, const float* __restrict__ bhh0,
                                const float* __restrict__ bih1, const float* __restrict__ bhh1) {
    int idx = blockIdx.x * blockDim.x + threadIdx.x;
    if (idx >= GHC) return;
    int o = (idx & 3) * HC + (idx >> 2);
    d_b0p[idx] = bih0[o] + bhh0[o];
    d_b1p[idx] = bih1[o] + bhh1[o];
}

__global__ void tok_kernel(const int* __restrict__ prev) {
    int r = blockIdx.x * blockDim.x + threadIdx.x;
    if (r >= GIN_ROWS_PAD) return;
    if (r < GIN_ROWS) {
        int k = r / (BB * JC);
        int bj = r - k * (BB * JC);
        int b = bj / JC;
        int j = bj - b * JC;
        int pin = j + k - 1; if (pin > T2C - 1) pin = T2C - 1;
        int tin = (k == 0) ? START_ID : prev[b * T2C + pin];
        d_ginoff[r] = tin * EC;
        int pt = j + k; if (pt > T2C - 1) pt = T2C - 1;
        d_tgttok[r] = prev[b * T2C + pt];
    } else {
        d_ginoff[r] = 0;
    }
}

__global__ void ctxoff_kernel() {
    int r = threadIdx.x;
    if (r < 256) {
        int b = r / T1C, t1 = r - b * T1C;
        d_ctxoff[r] = t1 * (BB * UC) + b * UC;
    }
}

__global__ void hcinit_kernel(const float* __restrict__ ench, const float* __restrict__ encc,
                              const float* __restrict__ Wph, const float* __restrict__ bph,
                              const float* __restrict__ Wpc, const float* __restrict__ bpc) {
    int idx = blockIdx.x * blockDim.x + threadIdx.x;
    if (idx >= 2 * BB * HC) return;
    int l = idx / (BB * HC);
    int b = (idx / HC) % BB;
    int h = idx % HC;
    const float4* eh = (const float4*)(ench + l * BB * UC + b * UC);
    const float4* ec = (const float4*)(encc + l * BB * UC + b * UC);
    const float4* wh = (const float4*)(Wph + (size_t)h * UC);
    const float4* wc = (const float4*)(Wpc + (size_t)h * UC);
    float sh = 0.f, sc = 0.f;
    for (int u = 0; u < UC / 4; u++) {
        float4 a = eh[u], w = wh[u];
        sh += a.x * w.x + a.y * w.y + a.z * w.z + a.w * w.w;
        float4 a2 = ec[u], w2 = wc[u];
        sc += a2.x * w2.x + a2.y * w2.y + a2.z * w2.z + a2.w * w2.w;
    }
    d_hinit[idx] = sh + bph[h];
    d_cinit[idx] = sc + bpc[h];
}

__global__ void initX_kernel() {
    int idx = blockIdx.x * blockDim.x + threadIdx.x;
    if (idx >= NN * HC) return;
    int n = idx >> 9, h = idx & 511;
    int b = n / (T1C * JC);
    d_X1[(size_t)n * 1024 + h]       = __float2bfloat16(d_hinit[b * HC + h]);
    d_X1[(size_t)n * 1024 + 512 + h] = __float2bfloat16(d_hinit[BB * HC + b * HC + h]);
    d_c0[idx] = d_cinit[b * HC + h];
    d_c1[idx] = d_cinit[BB * HC + b * HC + h];
    if (h == 0) d_cum[n] = 0.f;
}

// ---------------- bf16 TN GEMM, 128x128 tiles, single-sync 2-stage pipeline (R3/R7 config) ----
// EPI: 0 none, 1 +e1[n], 4 CELL0 (+gin+gctx, cell), 5 CELL1 (+e1[n], cell)
#define SASTRIDE 40
#define GSM_BYTES 67584
template <int EPI, bool GATHER, bool OBF>
__launch_bounds__(256)
__global__ void gemm_bf(const bf16* __restrict__ A, int lda,
                        const bf16* __restrict__ Bm, int ldb,
                        void* __restrict__ Cv, int ldc, int K,
                        const int* __restrict__ rowoff,
                        const float* __restrict__ e1, const float* __restrict__ e2,
                        int kstep, float* __restrict__ cptr, bf16* __restrict__ hout) {
    extern __shared__ char smraw[];
    bf16* sA = (bf16*)smraw;
    bf16* sB = sA + 2 * 128 * SASTRIDE;
    float* sC = (float*)smraw;

    int tid = threadIdx.x;
    int m0 = blockIdx.y * 128, n0 = blockIdx.x * 128;
    int wid = tid >> 5;
    int wm = wid & 1, wn = wid >> 1;

    wmma::fragment<wmma::accumulator, 16, 16, 16, float> acc[4][2];
#pragma unroll
    for (int mi = 0; mi < 4; mi++)
#pragma unroll
        for (int ni = 0; ni < 2; ni++) wmma::fill_fragment(acc[mi][ni], 0.0f);

    int nk = K >> 5;

#define GEMM_ISSUE(S)                                                                    \
    {                                                                                    \
        int buf_ = (S) & 1;                                                              \
        int k0_ = (S) << 5;                                                              \
        _Pragma("unroll")                                                                \
        for (int i_ = 0; i_ < 2; i_++) {                                                 \
            int idx_ = tid + i_ * 256;                                                   \
            int r_ = idx_ >> 2, c_ = idx_ & 3;                                           \
            const bf16* src_ = GATHER ? (A + rowoff[m0 + r_] + k0_ + c_ * 8)             \
                                      : (A + (size_t)(m0 + r_) * lda + k0_ + c_ * 8);    \
            cpa16(sA + buf_ * (128 * SASTRIDE) + r_ * SASTRIDE + c_ * 8, src_);          \
        }                                                                                \
        _Pragma("unroll")                                                                \
        for (int i_ = 0; i_ < 2; i_++) {                                                 \
            int idx_ = tid + i_ * 256;                                                   \
            int r_ = idx_ >> 2, c_ = idx_ & 3;                                           \
            cpa16(sB + buf_ * (128 * SASTRIDE) + r_ * SASTRIDE + c_ * 8,                 \
                  Bm + (size_t)(n0 + r_) * ldb + k0_ + c_ * 8);                          \
        }                                                                                \
        cpa_commit();                                                                    \
    }

    GEMM_ISSUE(0);
    for (int s = 0; s < nk; s++) {
        cpa_wait<0>();
        __syncthreads();
        if (s + 1 < nk) GEMM_ISSUE(s + 1);
        int buf = s & 1;
        const bf16* a_base = sA + buf * (128 * SASTRIDE);
        const bf16* b_base = sB + buf * (128 * SASTRIDE);
#pragma unroll
        for (int kk = 0; kk < 2; kk++) {
            wmma::fragment<wmma::matrix_a, 16, 16, 16, bf16, wmma::row_major> af[4];
            wmma::fragment<wmma::matrix_b, 16, 16, 16, bf16, wmma::col_major> bfr[2];
#pragma unroll
            for (int mi = 0; mi < 4; mi++)
                wmma::load_matrix_sync(af[mi], a_base + (wm * 64 + mi * 16) * SASTRIDE + kk * 16, SASTRIDE);
#pragma unroll
            for (int ni = 0; ni < 2; ni++)
                wmma::load_matrix_sync(bfr[ni], b_base + (wn * 32 + ni * 16) * SASTRIDE + kk * 16, SASTRIDE);
#pragma unroll
            for (int mi = 0; mi < 4; mi++)
#pragma unroll
                for (int ni = 0; ni < 2; ni++)
                    wmma::mma_sync(acc[mi][ni], af[mi], bfr[ni], acc[mi][ni]);
        }
    }
    __syncthreads();
#pragma unroll
    for (int mi = 0; mi < 4; mi++)
#pragma unroll
        for (int ni = 0; ni < 2; ni++)
            wmma::store_matrix_sync(sC + (wm * 64 + mi * 16) * 132 + wn * 32 + ni * 16,
                                    acc[mi][ni], 132, wmma::mem_row_major);
    __syncthreads();

#pragma unroll
    for (int i = 0; i < 16; i++) {
        int idx = tid + i * 256;
        int r = idx >> 5, c4 = idx & 31;
        float4 v = *(float4*)(sC + r * 132 + c4 * 4);
        int m = m0 + r;
        int nb = n0 + c4 * 4;
        if (EPI == 1 || EPI == 5) {
            float4 bb = *(const float4*)(e1 + nb);
            v.x += bb.x; v.y += bb.y; v.z += bb.z; v.w += bb.w;
        }
        if (EPI == 4) {
            int b = m / (T1C * JC);
            int rem = m - b * (T1C * JC);
            int t1 = rem / JC;
            int j = rem - t1 * JC;
            const float* gi = e1 + (size_t)((kstep * BB + b) * JC + j) * GHC + nb;
            const float* gc = e2 + (size_t)(b * T1C + t1) * GHC + nb;
            float4 a1 = *(const float4*)gi;
            float4 a2 = *(const float4*)gc;
            v.x += a1.x + a2.x; v.y += a1.y + a2.y; v.z += a1.z + a2.z; v.w += a1.w + a2.w;
        }
        if (EPI == 4 || EPI == 5) {
            int h = nb >> 2;
            size_t cix = (size_t)m * HC + h;
            float cold = cptr[cix];
            float cn = sigfast(v.y) * cold + sigfast(v.x) * tanha(v.z);
            cptr[cix] = cn;
            hout[(size_t)m * 1024 + h] = __float2bfloat16(sigfast(v.w) * tanha(cn));
        } else if (OBF) {
            bf162* p = (bf162*)((bf16*)Cv + (size_t)m * ldc + nb);
            p[0] = __floats2bfloat162_rn(v.x, v.y);
            p[1] = __floats2bfloat162_rn(v.z, v.w);
        } else {
            *(float4*)((float*)Cv + (size_t)m * ldc + nb) = v;
        }
    }
#undef GEMM_ISSUE
}

// ---------------- fused Wout GEMM (wmma bf16) + online logsumexp (R3/R7 proven config) ----
#define WA_STRIDE 264
#define WB_STRIDE 264
#define WOUT_SMEM_BYTES (64 * WA_STRIDE * 2 + 2 * 64 * WB_STRIDE * 2 + 64 * 72 * 4 + 64 * 5 * 4)
__launch_bounds__(256)
__global__ void wout_lse(const bf16* __restrict__ fco, const bf16* __restrict__ Wout,
                         const float* __restrict__ bout, const int* __restrict__ tgttok,
                         float* __restrict__ cum, float* __restrict__ outp, int kstep) {
    extern __shared__ char smraw[];
    bf16* A_s = (bf16*)smraw;
    bf16* B_s = A_s + 64 * WA_STRIDE;
    float* C_s = (float*)(B_s + 2 * 64 * WB_STRIDE);
    float* rM = C_s + 64 * 72;
    float* rS = rM + 64;
    float* rE = rS + 64;
    float* rT = rE + 64;
    int* rTgt = (int*)(rT + 64);

    int tid = threadIdx.x;
    int m0 = blockIdx.x * 64;

#pragma unroll
    for (int i = 0; i < 8; i++) {
        int idx = tid + i * 256;
        int r = idx >> 5, c = idx & 31;
        *(uint4*)(A_s + r * WA_STRIDE + c * 8) = *(const uint4*)(fco + (size_t)(m0 + r) * EC + c * 8);
    }
    if (tid < 64) {
        int n = m0 + tid;
        int b = n / (T1C * JC);
        int rem = n - b * (T1C * JC);
        int j = rem % JC;
        rTgt[tid] = tgttok[(kstep * BB + b) * JC + j];
        rM[tid] = -1e30f; rS[tid] = 0.f; rE[tid] = 0.f; rT[tid] = 0.f;
    }

    int wid = tid >> 5;
    int wm = wid & 1, wn = wid >> 1;

#define WOUT_ISSUE(S)                                                                  \
    {                                                                                  \
        int buf_ = (S) & 1;                                                            \
        _Pragma("unroll")                                                              \
        for (int i_ = 0; i_ < 8; i_++) {                                               \
            int idx_ = tid + i_ * 256;                                                 \
            int r_ = idx_ >> 5, c_ = idx_ & 31;                                        \
            cpa16(B_s + buf_ * (64 * WB_STRIDE) + r_ * WB_STRIDE + c_ * 8,             \
                  Wout + (size_t)((S) * 64 + r_) * EC + c_ * 8);                       \
        }                                                                              \
        cpa_commit();                                                                  \
    }

    WOUT_ISSUE(0);
    const int NCC = VC / 64;
    for (int nc = 0; nc < NCC; nc++) {
        cpa_wait<0>();
        __syncthreads();
        if (nc + 1 < NCC) WOUT_ISSUE(nc + 1);
        int buf = nc & 1;
        const bf16* b_base = B_s + buf * (64 * WB_STRIDE);

        wmma::fragment<wmma::accumulator, 16, 16, 16, float> acc[2];
        wmma::fill_fragment(acc[0], 0.0f);
        wmma::fill_fragment(acc[1], 0.0f);
#pragma unroll
        for (int kk = 0; kk < 16; kk++) {
            wmma::fragment<wmma::matrix_a, 16, 16, 16, bf16, wmma::row_major> af[2];
            wmma::fragment<wmma::matrix_b, 16, 16, 16, bf16, wmma::col_major> bfr;
            wmma::load_matrix_sync(af[0], A_s + (wm * 32) * WA_STRIDE + kk * 16, WA_STRIDE);
            wmma::load_matrix_sync(af[1], A_s + (wm * 32 + 16) * WA_STRIDE + kk * 16, WA_STRIDE);
            wmma::load_matrix_sync(bfr, b_base + (wn * 16) * WB_STRIDE + kk * 16, WB_STRIDE);
            wmma::mma_sync(acc[0], af[0], bfr, acc[0]);
            wmma::mma_sync(acc[1], af[1], bfr, acc[1]);
        }
        wmma::store_matrix_sync(C_s + (wm * 32) * 72 + wn * 16, acc[0], 72, wmma::mem_row_major);
        wmma::store_matrix_sync(C_s + (wm * 32 + 16) * 72 + wn * 16, acc[1], 72, wmma::mem_row_major);
        __syncthreads();

        {
            int n0v = nc * 64;
            int r = tid >> 2, q = tid & 3;
            int tgt = rTgt[r];
            float lv[16];
            float lm = -1e30f;
#pragma unroll
            for (int c = 0; c < 16; c++) {
                int col = q * 16 + c;
                int gcol = n0v + col;
                float l = C_s[r * 72 + col] + bout[gcol];
                lv[c] = l;
                lm = fmaxf(lm, l);
                if (gcol == 2) rE[r] = l;
                if (gcol == tgt) rT[r] = l;
            }
            float ls = 0.f;
#pragma unroll
            for (int c = 0; c < 16; c++) ls += __expf(lv[c] - lm);
#pragma unroll
            for (int off = 1; off < 4; off <<= 1) {
                float om = __shfl_xor_sync(0xffffffffu, lm, off);
                float os = __shfl_xor_sync(0xffffffffu, ls, off);
                float nm = fmaxf(lm, om);
                ls = ls * __expf(lm - nm) + os * __expf(om - nm);
                lm = nm;
            }
            if (q == 0) {
                float M = rM[r], S = rS[r];
                float nm = fmaxf(M, lm);
                rS[r] = S * __expf(M - nm) + ls * __expf(lm - nm);
                rM[r] = nm;
            }
        }
        __syncthreads();
    }

    if (tid < 64) {
        int n = m0 + tid;
        float lse = rM[tid] + logf(rS[tid]);
        int j = n % JC;
        bool valid = (j + kstep) <= T2C;
        float cv = cum[n];
        outp[(size_t)n * KSEG + kstep] = valid ? (cv + rE[tid] - lse) : -1e9f;
        cum[n] = cv + rT[tid] - lse;
    }
#undef WOUT_ISSUE
}

// ---------------- host launch ----------------
static inline float* fsym(const void* sym) {
    void* p = nullptr; cudaGetSymbolAddress(&p, sym); return (float*)p;
}
static inline bf16* bsym(const void* sym) {
    void* p = nullptr; cudaGetSymbolAddress(&p, sym); return (bf16*)p;
}
static inline int* isym(const void* sym) {
    void* p = nullptr; cudaGetSymbolAddress(&p, sym); return (int*)p;
}

extern "C" void kernel_launch(void* const* d_in, const int* in_sizes, int n_in,
                              void* d_out, int out_size) {
    const int*   prev   = (const int*)d_in[0];
    const float* encO   = (const float*)d_in[1];
    const float* encH   = (const float*)d_in[2];
    const float* encC   = (const float*)d_in[3];
    const float* embed  = (const float*)d_in[4];
    const float* Wph    = (const float*)d_in[5];
    const float* bph    = (const float*)d_in[6];
    const float* Wpc    = (const float*)d_in[7];
    const float* bpc    = (const float*)d_in[8];
    const float* Wih0   = (const float*)d_in[9];
    const float* Whh0   = (const float*)d_in[10];
    const float* bih0   = (const float*)d_in[11];
    const float* bhh0   = (const float*)d_in[12];
    const float* Wih1   = (const float*)d_in[13];
    const float* Whh1   = (const float*)d_in[14];
    const float* bih1   = (const float*)d_in[15];
    const float* bhh1   = (const float*)d_in[16];
    const float* Wfc    = (const float*)d_in[17];
    const float* bfc    = (const float*)d_in[18];
    const float* Wout   = (const float*)d_in[19];
    const float* bout   = (const float*)d_in[20];
    float* outp = (float*)d_out;

    bf16*  pX1   = bsym(d_X1);
    float* pc0   = fsym(d_c0);
    float* pc1   = fsym(d_c1);
    bf16*  pfco  = bsym(d_fco);
    float* pgin  = fsym(d_gin);
    float* pgctx = fsym(d_gctx);
    bf16*  pctxb = bsym(d_ctxb);
    float* pcum  = fsym(d_cum);
    float* pb0p  = fsym(d_b0p);
    float* pb1p  = fsym(d_b1p);
    int*   pgoff = isym(d_ginoff);
    int*   pcoff = isym(d_ctxoff);
    int*   ptgt  = isym(d_tgttok);
    bf16*  pWhh0b  = bsym(d_Whh0b);
    bf16*  pW1catb = bsym(d_W1catb);
    bf16*  pWfcb   = bsym(d_Wfcb);
    bf16*  pWoutb  = bsym(d_Woutb);
    bf16*  pembb   = bsym(d_embb);
    bf16*  pWih0b  = bsym(d_Wih0b);
    bf16*  pWphb   = bsym(d_Wphb);
    bf16*  pencOb  = bsym(d_encOb);

    // one-time stream/event setup (topology identical every capture)
    static bool s_init = false;
    static cudaStream_t sW;
    static cudaEvent_t evG1[KSEG], evFc[KSEG], evW[KSEG];
    if (!s_init) {
        cudaStreamCreateWithFlags(&sW, cudaStreamNonBlocking);
        for (int i = 0; i < KSEG; i++) {
            cudaEventCreateWithFlags(&evG1[i], cudaEventDisableTiming);
            cudaEventCreateWithFlags(&evFc[i], cudaEventDisableTiming);
            cudaEventCreateWithFlags(&evW[i], cudaEventDisableTiming);
        }
        s_init = true;
    }

    cudaFuncSetAttribute(gemm_bf<0, true,  false>, cudaFuncAttributeMaxDynamicSharedMemorySize, GSM_BYTES);
    cudaFuncSetAttribute(gemm_bf<1, true,  true >, cudaFuncAttributeMaxDynamicSharedMemorySize, GSM_BYTES);
    cudaFuncSetAttribute(gemm_bf<1, false, false>, cudaFuncAttributeMaxDynamicSharedMemorySize, GSM_BYTES);
    cudaFuncSetAttribute(gemm_bf<1, false, true >, cudaFuncAttributeMaxDynamicSharedMemorySize, GSM_BYTES);
    cudaFuncSetAttribute(gemm_bf<4, false, false>, cudaFuncAttributeMaxDynamicSharedMemorySize, GSM_BYTES);
    cudaFuncSetAttribute(gemm_bf<5, false, false>, cudaFuncAttributeMaxDynamicSharedMemorySize, GSM_BYTES);
    cudaFuncSetAttribute(wout_lse, cudaFuncAttributeMaxDynamicSharedMemorySize, WOUT_SMEM_BYTES);

    // ---- prologue: conversions / permutations ----
    wperm_kernel<<<(GHC * HC + 255) / 256, 256>>>(Whh0, pWhh0b, HC);
    w1catperm_kernel<<<(GHC * 1024 + 255) / 256, 256>>>(Wih1, Whh1);
    wperm_kernel<<<(GHC * (EC + HC) + 255) / 256, 256>>>(Wih0, pWih0b, EC + HC);
    biasperm_kernel<<<(GHC + 255) / 256, 256>>>(bih0, bhh0, bih1, bhh1);
    cvt_kernel<<<(EC * HC / 4 + 255) / 256, 256>>>(Wfc, pWfcb, EC * HC / 4);
    cvt_kernel<<<(VC * EC / 4 + 255) / 256, 256>>>(Wout, pWoutb, VC * EC / 4);
    cvt_kernel<<<((VC + 2) * EC / 4 + 255) / 256, 256>>>(embed, pembb, (VC + 2) * EC / 4);
    cvt_kernel<<<(HC * UC / 4 + 255) / 256, 256>>>(Wph, pWphb, HC * UC / 4);
    cvt_kernel<<<(T1C * BB * UC / 4 + 255) / 256, 256>>>(encO, pencOb, T1C * BB * UC / 4);

    tok_kernel<<<(GIN_ROWS_PAD + 255) / 256, 256>>>(prev);
    ctxoff_kernel<<<1, 256>>>();
    hcinit_kernel<<<(2 * BB * HC + 255) / 256, 256>>>(encH, encC, Wph, bph, Wpc, bpc);
    initX_kernel<<<(NN * HC) / 256, 256>>>();

    // ctx(bf16) = encO @ Wph^T + bph : M=256, N=512, K=1024 (gather A)
    gemm_bf<1, true, true><<<dim3(512 / 128, 256 / 128), 256, GSM_BYTES>>>(
        pencOb, 0, pWphb, UC, pctxb, HC, UC, pcoff, bph, nullptr, 0, nullptr, nullptr);
    // gctx = ctx @ Wih0p[:,E:]^T + b0p : M=256, N=2048(perm), K=512
    gemm_bf<1, false, false><<<dim3(GHC / 128, 256 / 128), 256, GSM_BYTES>>>(
        pctxb, HC, pWih0b + EC, EC + HC, pgctx, GHC, HC, nullptr, pb0p, nullptr, 0, nullptr, nullptr);
    // gin = emb @ Wih0p[:, :E]^T : M=2432, N=2048(perm), K=256 (gather A)
    gemm_bf<0, true, false><<<dim3(GHC / 128, GIN_ROWS_PAD / 128), 256, GSM_BYTES>>>(
        pembb, 0, pWih0b, EC + HC, pgin, GHC, EC, pgoff, nullptr, nullptr, 0, nullptr, nullptr);

    for (int k = 0; k < KSEG; k++) {
        bf16* fcobuf = pfco + (size_t)(k & 1) * NN * EC;
        // layer 0 (s0): g0 = h0 @ Whh0p^T + gin + gctx, fused cell -> c0, h0.
        // Touches only h0/c0 — safe to run concurrently with fc(k-1)/wout(k-1) on sW.
        gemm_bf<4, false, false><<<dim3(GHC / 128, NN / 128), 256, GSM_BYTES>>>(
            pX1, 1024, pWhh0b, HC, nullptr, 0, HC, nullptr, pgin, pgctx, k, pc0, pX1);
        // layer 1 (s0): writes h1 — must wait until fc(k-1) on sW finished READING h1.
        if (k >= 1) cudaStreamWaitEvent(0, evFc[k - 1], 0);
        gemm_bf<5, false, false><<<dim3(GHC / 128, NN / 128), 256, GSM_BYTES>>>(
            pX1, 1024, pW1catb, 1024, nullptr, 0, 1024, nullptr, pb1p, nullptr, k, pc1, pX1 + 512);
        cudaEventRecord(evG1[k], 0);

        // fc(k) + wout(k) on side stream: depends only on g1(k); fco buffer reuse
        // (k vs k-2) is ordered by same-stream FIFO on sW.
        cudaStreamWaitEvent(sW, evG1[k], 0);
        gemm_bf<1, false, true><<<dim3(EC / 128, NN / 128), 256, GSM_BYTES, sW>>>(
            pX1 + 512, 1024, pWfcb, HC, fcobuf, EC, HC, nullptr, bfc, nullptr, 0, nullptr, nullptr);
        cudaEventRecord(evFc[k], sW);
        wout_lse<<<NN / 64, 256, WOUT_SMEM_BYTES, sW>>>(fcobuf, pWoutb, bout, ptgt, pcum, outp, k);
        cudaEventRecord(evW[k], sW);
    }
    // graph sink must depend on the last wout
    cudaStreamWaitEvent(0, evW[KSEG - 1], 0);
}

// round 12
// speedup vs baseline: 1.8468x; 1.3101x over previous
#include <cuda_runtime.h>
#include <cuda_fp16.h>
#include <mma.h>
#include <math.h>
#include <stdint.h>

using namespace nvcuda;

// ---------------- problem constants ----------------
#define BB 8
#define T1C 32
#define T2C 32
#define JC 33
#define KSEG 9
#define NN 8448
#define EC 256
#define HC 512
#define UC 1024
#define GHC 2048
#define VC 8000
#define START_ID 8001
#define GIN_ROWS 2376
#define GIN_ROWS_PAD 2432

typedef __half hf;
typedef __half2 hf2;

// ---------------- device scratch ----------------
__device__ hf    d_X1[NN * 1024];             // [h0 | h1] per row (fp16)
__device__ float d_c0[NN * HC];
__device__ float d_c1[NN * HC];
__device__ hf    d_fco[2 * NN * EC];          // double-buffered across steps
__device__ float d_gin[GIN_ROWS_PAD * GHC];
__device__ float d_gctx[256 * GHC];
__device__ hf    d_ctxb[256 * HC];
__device__ float d_hinit[2 * BB * HC];
__device__ float d_cinit[2 * BB * HC];
__device__ float d_cum[NN];
__device__ float d_b0p[GHC];
__device__ float d_b1p[GHC];
__device__ int   d_ginoff[GIN_ROWS_PAD];
__device__ int   d_ctxoff[256];
__device__ int   d_tgttok[GIN_ROWS];
__device__ hf d_Whh0b[GHC * HC];
__device__ hf d_W1catb[GHC * 1024];
__device__ hf d_Wfcb[EC * HC];
__device__ hf d_Woutb[VC * EC];
__device__ hf d_embb[(VC + 2) * EC];
__device__ hf d_Wih0b[GHC * (EC + HC)];
__device__ hf d_Wphb[HC * UC];
__device__ hf d_encOb[T1C * BB * UC];

__device__ __forceinline__ float tanha(float x) {
    float y; asm("tanh.approx.f32 %0, %1;" : "=f"(y) : "f"(x)); return y;
}
__device__ __forceinline__ float sigfast(float x) { return 0.5f * tanha(0.5f * x) + 0.5f; }

__device__ __forceinline__ void cpa16(void* dst, const void* src) {
    uint32_t d = (uint32_t)__cvta_generic_to_shared(dst);
    asm volatile("cp.async.cg.shared.global [%0], [%1], 16;\n" :: "r"(d), "l"(src));
}
__device__ __forceinline__ void cpa_commit() { asm volatile("cp.async.commit_group;\n"); }
template <int N> __device__ __forceinline__ void cpa_wait() {
    asm volatile("cp.async.wait_group %0;\n" :: "n"(N));
}

// ---------------- prologue kernels ----------------
__global__ void cvt_kernel(const float* __restrict__ src, hf* __restrict__ dst, int n4) {
    int i = blockIdx.x * blockDim.x + threadIdx.x;
    if (i >= n4) return;
    float4 v = ((const float4*)src)[i];
    hf2* d = (hf2*)dst + i * 2;
    d[0] = __floats2half2_rn(v.x, v.y);
    d[1] = __floats2half2_rn(v.z, v.w);
}

__global__ void wperm_kernel(const float* __restrict__ W, hf* __restrict__ dst, int ldw) {
    int idx = blockIdx.x * blockDim.x + threadIdx.x;
    if (idx >= GHC * ldw) return;
    int np = idx / ldw, c = idx - np * ldw;
    int h = np >> 2, gate = np & 3;
    dst[idx] = __float2half(W[(size_t)(gate * HC + h) * ldw + c]);
}

__global__ void w1catperm_kernel(const float* __restrict__ Wih1, const float* __restrict__ Whh1) {
    int idx = blockIdx.x * blockDim.x + threadIdx.x;
    if (idx >= GHC * 1024) return;
    int np = idx >> 10, c = idx & 1023;
    int o = (np & 3) * HC + (np >> 2);
    float v = (c < HC) ? Wih1[(size_t)o * HC + c] : Whh1[(size_t)o * HC + (c - HC)];
    d_W1catb[idx] = __float2half(v);
}

__global__ void biasperm_kernel(const float* __restrict__ bih0, const float* __restrict__ bhh0,
                                const float* __restrict__ bih1, const float* __restrict__ bhh1) {
    int idx = blockIdx.x * blockDim.x + threadIdx.x;
    if (idx >= GHC) return;
    int o = (idx & 3) * HC + (idx >> 2);
    d_b0p[idx] = bih0[o] + bhh0[o];
    d_b1p[idx] = bih1[o] + bhh1[o];
}

__global__ void tok_kernel(const int* __restrict__ prev) {
    int r = blockIdx.x * blockDim.x + threadIdx.x;
    if (r >= GIN_ROWS_PAD) return;
    if (r < GIN_ROWS) {
        int k = r / (BB * JC);
        int bj = r - k * (BB * JC);
        int b = bj / JC;
        int j = bj - b * JC;
        int pin = j + k - 1; if (pin > T2C - 1) pin = T2C - 1;
        int tin = (k == 0) ? START_ID : prev[b * T2C + pin];
        d_ginoff[r] = tin * EC;
        int pt = j + k; if (pt > T2C - 1) pt = T2C - 1;
        d_tgttok[r] = prev[b * T2C + pt];
    } else {
        d_ginoff[r] = 0;
    }
}

__global__ void ctxoff_kernel() {
    int r = threadIdx.x;
    if (r < 256) {
        int b = r / T1C, t1 = r - b * T1C;
        d_ctxoff[r] = t1 * (BB * UC) + b * UC;
    }
}

__global__ void hcinit_kernel(const float* __restrict__ ench, const float* __restrict__ encc,
                              const float* __restrict__ Wph, const float* __restrict__ bph,
                              const float* __restrict__ Wpc, const float* __restrict__ bpc) {
    int idx = blockIdx.x * blockDim.x + threadIdx.x;
    if (idx >= 2 * BB * HC) return;
    int l = idx / (BB * HC);
    int b = (idx / HC) % BB;
    int h = idx % HC;
    const float4* eh = (const float4*)(ench + l * BB * UC + b * UC);
    const float4* ec = (const float4*)(encc + l * BB * UC + b * UC);
    const float4* wh = (const float4*)(Wph + (size_t)h * UC);
    const float4* wc = (const float4*)(Wpc + (size_t)h * UC);
    float sh = 0.f, sc = 0.f;
    for (int u = 0; u < UC / 4; u++) {
        float4 a = eh[u], w = wh[u];
        sh += a.x * w.x + a.y * w.y + a.z * w.z + a.w * w.w;
        float4 a2 = ec[u], w2 = wc[u];
        sc += a2.x * w2.x + a2.y * w2.y + a2.z * w2.z + a2.w * w2.w;
    }
    d_hinit[idx] = sh + bph[h];
    d_cinit[idx] = sc + bpc[h];
}

__global__ void initX_kernel() {
    int idx = blockIdx.x * blockDim.x + threadIdx.x;
    if (idx >= NN * HC) return;
    int n = idx >> 9, h = idx & 511;
    int b = n / (T1C * JC);
    d_X1[(size_t)n * 1024 + h]       = __float2half(d_hinit[b * HC + h]);
    d_X1[(size_t)n * 1024 + 512 + h] = __float2half(d_hinit[BB * HC + b * HC + h]);
    d_c0[idx] = d_cinit[b * HC + h];
    d_c1[idx] = d_cinit[BB * HC + b * HC + h];
    if (h == 0) d_cum[n] = 0.f;
}

// ---------------- fp16 TN GEMM (f16 accumulate), 128x128 tiles, 2-stage pipeline ----
// EPI: 0 none, 1 +e1[n], 4 CELL0 (+gin+gctx, cell), 5 CELL1 (+e1[n], cell)
// OBF: write half output, else fp32
#define SASTRIDE 40
#define CSTRIDE 136
#define GSM_BYTES 40960     // sA/sB 2-stage dominate; sC overlay 128*136*2=34816
template <int EPI, bool GATHER, bool OBF>
__launch_bounds__(256)
__global__ void gemm_hf(const hf* __restrict__ A, int lda,
                        const hf* __restrict__ Bm, int ldb,
                        void* __restrict__ Cv, int ldc, int K,
                        const int* __restrict__ rowoff,
                        const float* __restrict__ e1, const float* __restrict__ e2,
                        int kstep, float* __restrict__ cptr, hf* __restrict__ hout) {
    extern __shared__ char smraw[];
    hf* sA = (hf*)smraw;
    hf* sB = sA + 2 * 128 * SASTRIDE;
    hf* sC = (hf*)smraw;                      // 128 x 136 overlay

    int tid = threadIdx.x;
    int m0 = blockIdx.y * 128, n0 = blockIdx.x * 128;
    int wid = tid >> 5;
    int wm = wid & 1, wn = wid >> 1;          // warp tile 64(m) x 32(n)

    wmma::fragment<wmma::accumulator, 16, 16, 16, hf> acc[4][2];
#pragma unroll
    for (int mi = 0; mi < 4; mi++)
#pragma unroll
        for (int ni = 0; ni < 2; ni++) wmma::fill_fragment(acc[mi][ni], __float2half(0.0f));

    int nk = K >> 5;

#define GEMM_ISSUE(S)                                                                    \
    {                                                                                    \
        int buf_ = (S) & 1;                                                              \
        int k0_ = (S) << 5;                                                              \
        _Pragma("unroll")                                                                \
        for (int i_ = 0; i_ < 2; i_++) {                                                 \
            int idx_ = tid + i_ * 256;                                                   \
            int r_ = idx_ >> 2, c_ = idx_ & 3;                                           \
            const hf* src_ = GATHER ? (A + rowoff[m0 + r_] + k0_ + c_ * 8)               \
                                    : (A + (size_t)(m0 + r_) * lda + k0_ + c_ * 8);      \
            cpa16(sA + buf_ * (128 * SASTRIDE) + r_ * SASTRIDE + c_ * 8, src_);          \
        }                                                                                \
        _Pragma("unroll")                                                                \
        for (int i_ = 0; i_ < 2; i_++) {                                                 \
            int idx_ = tid + i_ * 256;                                                   \
            int r_ = idx_ >> 2, c_ = idx_ & 3;                                           \
            cpa16(sB + buf_ * (128 * SASTRIDE) + r_ * SASTRIDE + c_ * 8,                 \
                  Bm + (size_t)(n0 + r_) * ldb + k0_ + c_ * 8);                          \
        }                                                                                \
        cpa_commit();                                                                    \
    }

    GEMM_ISSUE(0);
    for (int s = 0; s < nk; s++) {
        cpa_wait<0>();
        __syncthreads();
        if (s + 1 < nk) GEMM_ISSUE(s + 1);
        int buf = s & 1;
        const hf* a_base = sA + buf * (128 * SASTRIDE);
        const hf* b_base = sB + buf * (128 * SASTRIDE);
#pragma unroll
        for (int kk = 0; kk < 2; kk++) {
            wmma::fragment<wmma::matrix_a, 16, 16, 16, hf, wmma::row_major> af[4];
            wmma::fragment<wmma::matrix_b, 16, 16, 16, hf, wmma::col_major> bfr[2];
#pragma unroll
            for (int mi = 0; mi < 4; mi++)
                wmma::load_matrix_sync(af[mi], a_base + (wm * 64 + mi * 16) * SASTRIDE + kk * 16, SASTRIDE);
#pragma unroll
            for (int ni = 0; ni < 2; ni++)
                wmma::load_matrix_sync(bfr[ni], b_base + (wn * 32 + ni * 16) * SASTRIDE + kk * 16, SASTRIDE);
#pragma unroll
            for (int mi = 0; mi < 4; mi++)
#pragma unroll
                for (int ni = 0; ni < 2; ni++)
                    wmma::mma_sync(acc[mi][ni], af[mi], bfr[ni], acc[mi][ni]);
        }
    }
    __syncthreads();
#pragma unroll
    for (int mi = 0; mi < 4; mi++)
#pragma unroll
        for (int ni = 0; ni < 2; ni++)
            wmma::store_matrix_sync(sC + (wm * 64 + mi * 16) * CSTRIDE + wn * 32 + ni * 16,
                                    acc[mi][ni], CSTRIDE, wmma::mem_row_major);
    __syncthreads();

#pragma unroll
    for (int i = 0; i < 16; i++) {       // 128x128 halves; 4 per thread-iter
        int idx = tid + i * 256;
        int r = idx >> 5, c4 = idx & 31;
        uint2 raw = *(uint2*)(sC + r * CSTRIDE + c4 * 4);
        hf2 p0 = *(hf2*)&raw.x;
        hf2 p1 = *(hf2*)&raw.y;
        float4 v = make_float4(__low2float(p0), __high2float(p0),
                               __low2float(p1), __high2float(p1));
        int m = m0 + r;
        int nb = n0 + c4 * 4;
        if (EPI == 1 || EPI == 5) {
            float4 bb = *(const float4*)(e1 + nb);
            v.x += bb.x; v.y += bb.y; v.z += bb.z; v.w += bb.w;
        }
        if (EPI == 4) {
            int b = m / (T1C * JC);
            int rem = m - b * (T1C * JC);
            int t1 = rem / JC;
            int j = rem - t1 * JC;
            const float* gi = e1 + (size_t)((kstep * BB + b) * JC + j) * GHC + nb;
            const float* gc = e2 + (size_t)(b * T1C + t1) * GHC + nb;
            float4 a1 = *(const float4*)gi;
            float4 a2 = *(const float4*)gc;
            v.x += a1.x + a2.x; v.y += a1.y + a2.y; v.z += a1.z + a2.z; v.w += a1.w + a2.w;
        }
        if (EPI == 4 || EPI == 5) {
            int h = nb >> 2;
            size_t cix = (size_t)m * HC + h;
            float cold = cptr[cix];
            float cn = sigfast(v.y) * cold + sigfast(v.x) * tanha(v.z);
            cptr[cix] = cn;
            hout[(size_t)m * 1024 + h] = __float2half(sigfast(v.w) * tanha(cn));
        } else if (OBF) {
            hf2* p = (hf2*)((hf*)Cv + (size_t)m * ldc + nb);
            p[0] = __floats2half2_rn(v.x, v.y);
            p[1] = __floats2half2_rn(v.z, v.w);
        } else {
            *(float4*)((float*)Cv + (size_t)m * ldc + nb) = v;
        }
    }
#undef GEMM_ISSUE
}

// ---------------- fused Wout GEMM (fp16/f16-acc) + online logsumexp ----------------
#define WA_STRIDE 264
#define WB_STRIDE 264
#define WC_STRIDE 72
#define WOUT_SMEM_BYTES (64 * WA_STRIDE * 2 + 2 * 64 * WB_STRIDE * 2 + 64 * WC_STRIDE * 2 + 64 * 5 * 4)
__launch_bounds__(256)
__global__ void wout_lse(const hf* __restrict__ fco, const hf* __restrict__ Wout,
                         const float* __restrict__ bout, const int* __restrict__ tgttok,
                         float* __restrict__ cum, float* __restrict__ outp, int kstep) {
    extern __shared__ char smraw[];
    hf* A_s = (hf*)smraw;                            // 64 x 264
    hf* B_s = A_s + 64 * WA_STRIDE;                  // 2 x 64 x 264
    hf* C_s = B_s + 2 * 64 * WB_STRIDE;              // 64 x 72 (half)
    float* rM = (float*)(C_s + 64 * WC_STRIDE);
    float* rS = rM + 64;
    float* rE = rS + 64;
    float* rT = rE + 64;
    int* rTgt = (int*)(rT + 64);

    int tid = threadIdx.x;
    int m0 = blockIdx.x * 64;

#pragma unroll
    for (int i = 0; i < 8; i++) {        // A: 64 x 256 halves
        int idx = tid + i * 256;
        int r = idx >> 5, c = idx & 31;
        *(uint4*)(A_s + r * WA_STRIDE + c * 8) = *(const uint4*)(fco + (size_t)(m0 + r) * EC + c * 8);
    }
    if (tid < 64) {
        int n = m0 + tid;
        int b = n / (T1C * JC);
        int rem = n - b * (T1C * JC);
        int j = rem % JC;
        rTgt[tid] = tgttok[(kstep * BB + b) * JC + j];
        rM[tid] = -1e30f; rS[tid] = 0.f; rE[tid] = 0.f; rT[tid] = 0.f;
    }

    int wid = tid >> 5;
    int wm = wid & 1, wn = wid >> 1;     // warp tile 32(m) x 16(n)

#define WOUT_ISSUE(S)                                                                  \
    {                                                                                  \
        int buf_ = (S) & 1;                                                            \
        _Pragma("unroll")                                                              \
        for (int i_ = 0; i_ < 8; i_++) {                                               \
            int idx_ = tid + i_ * 256;                                                 \
            int r_ = idx_ >> 5, c_ = idx_ & 31;                                        \
            cpa16(B_s + buf_ * (64 * WB_STRIDE) + r_ * WB_STRIDE + c_ * 8,             \
                  Wout + (size_t)((S) * 64 + r_) * EC + c_ * 8);                       \
        }                                                                              \
        cpa_commit();                                                                  \
    }

    WOUT_ISSUE(0);
    const int NCC = VC / 64;
    for (int nc = 0; nc < NCC; nc++) {
        cpa_wait<0>();
        __syncthreads();
        if (nc + 1 < NCC) WOUT_ISSUE(nc + 1);
        int buf = nc & 1;
        const hf* b_base = B_s + buf * (64 * WB_STRIDE);

        wmma::fragment<wmma::accumulator, 16, 16, 16, hf> acc[2];
        wmma::fill_fragment(acc[0], __float2half(0.0f));
        wmma::fill_fragment(acc[1], __float2half(0.0f));
#pragma unroll
        for (int kk = 0; kk < 16; kk++) {
            wmma::fragment<wmma::matrix_a, 16, 16, 16, hf, wmma::row_major> af[2];
            wmma::fragment<wmma::matrix_b, 16, 16, 16, hf, wmma::col_major> bfr;
            wmma::load_matrix_sync(af[0], A_s + (wm * 32) * WA_STRIDE + kk * 16, WA_STRIDE);
            wmma::load_matrix_sync(af[1], A_s + (wm * 32 + 16) * WA_STRIDE + kk * 16, WA_STRIDE);
            wmma::load_matrix_sync(bfr, b_base + (wn * 16) * WB_STRIDE + kk * 16, WB_STRIDE);
            wmma::mma_sync(acc[0], af[0], bfr, acc[0]);
            wmma::mma_sync(acc[1], af[1], bfr, acc[1]);
        }
        wmma::store_matrix_sync(C_s + (wm * 32) * WC_STRIDE + wn * 16, acc[0], WC_STRIDE, wmma::mem_row_major);
        wmma::store_matrix_sync(C_s + (wm * 32 + 16) * WC_STRIDE + wn * 16, acc[1], WC_STRIDE, wmma::mem_row_major);
        __syncthreads();

        {   // two-pass LSE over this 64-col chunk: 4 lanes per row, 16 cols each
            int n0v = nc * 64;
            int r = tid >> 2, q = tid & 3;
            int tgt = rTgt[r];
            float lv[16];
            float lm = -1e30f;
#pragma unroll
            for (int c = 0; c < 16; c++) {
                int col = q * 16 + c;
                int gcol = n0v + col;
                float l = __half2float(C_s[r * WC_STRIDE + col]) + bout[gcol];
                lv[c] = l;
                lm = fmaxf(lm, l);
                if (gcol == 2) rE[r] = l;
                if (gcol == tgt) rT[r] = l;
            }
            float ls = 0.f;
#pragma unroll
            for (int c = 0; c < 16; c++) ls += __expf(lv[c] - lm);
#pragma unroll
            for (int off = 1; off < 4; off <<= 1) {
                float om = __shfl_xor_sync(0xffffffffu, lm, off);
                float os = __shfl_xor_sync(0xffffffffu, ls, off);
                float nm = fmaxf(lm, om);
                ls = ls * __expf(lm - nm) + os * __expf(om - nm);
                lm = nm;
            }
            if (q == 0) {
                float M = rM[r], S = rS[r];
                float nm = fmaxf(M, lm);
                rS[r] = S * __expf(M - nm) + ls * __expf(lm - nm);
                rM[r] = nm;
            }
        }
        __syncthreads();
    }

    if (tid < 64) {
        int n = m0 + tid;
        float lse = rM[tid] + logf(rS[tid]);
        int j = n % JC;
        bool valid = (j + kstep) <= T2C;
        float cv = cum[n];
        outp[(size_t)n * KSEG + kstep] = valid ? (cv + rE[tid] - lse) : -1e9f;
        cum[n] = cv + rT[tid] - lse;
    }
#undef WOUT_ISSUE
}

// ---------------- host launch ----------------
static inline float* fsym(const void* sym) {
    void* p = nullptr; cudaGetSymbolAddress(&p, sym); return (float*)p;
}
static inline hf* hsym(const void* sym) {
    void* p = nullptr; cudaGetSymbolAddress(&p, sym); return (hf*)p;
}
static inline int* isym(const void* sym) {
    void* p = nullptr; cudaGetSymbolAddress(&p, sym); return (int*)p;
}

extern "C" void kernel_launch(void* const* d_in, const int* in_sizes, int n_in,
                              void* d_out, int out_size) {
    const int*   prev   = (const int*)d_in[0];
    const float* encO   = (const float*)d_in[1];
    const float* encH   = (const float*)d_in[2];
    const float* encC   = (const float*)d_in[3];
    const float* embed  = (const float*)d_in[4];
    const float* Wph    = (const float*)d_in[5];
    const float* bph    = (const float*)d_in[6];
    const float* Wpc    = (const float*)d_in[7];
    const float* bpc    = (const float*)d_in[8];
    const float* Wih0   = (const float*)d_in[9];
    const float* Whh0   = (const float*)d_in[10];
    const float* bih0   = (const float*)d_in[11];
    const float* bhh0   = (const float*)d_in[12];
    const float* Wih1   = (const float*)d_in[13];
    const float* Whh1   = (const float*)d_in[14];
    const float* bih1   = (const float*)d_in[15];
    const float* bhh1   = (const float*)d_in[16];
    const float* Wfc    = (const float*)d_in[17];
    const float* bfc    = (const float*)d_in[18];
    const float* Wout   = (const float*)d_in[19];
    const float* bout   = (const float*)d_in[20];
    float* outp = (float*)d_out;

    hf*    pX1   = hsym(d_X1);
    float* pc0   = fsym(d_c0);
    float* pc1   = fsym(d_c1);
    hf*    pfco  = hsym(d_fco);
    float* pgin  = fsym(d_gin);
    float* pgctx = fsym(d_gctx);
    hf*    pctxb = hsym(d_ctxb);
    float* pcum  = fsym(d_cum);
    float* pb0p  = fsym(d_b0p);
    float* pb1p  = fsym(d_b1p);
    int*   pgoff = isym(d_ginoff);
    int*   pcoff = isym(d_ctxoff);
    int*   ptgt  = isym(d_tgttok);
    hf*    pWhh0b  = hsym(d_Whh0b);
    hf*    pW1catb = hsym(d_W1catb);
    hf*    pWfcb   = hsym(d_Wfcb);
    hf*    pWoutb  = hsym(d_Woutb);
    hf*    pembb   = hsym(d_embb);
    hf*    pWih0b  = hsym(d_Wih0b);
    hf*    pWphb   = hsym(d_Wphb);
    hf*    pencOb  = hsym(d_encOb);

    // one-time stream/event setup (topology identical every capture)
    static bool s_init = false;
    static cudaStream_t sW;
    static cudaEvent_t evG1[KSEG], evFc[KSEG], evW[KSEG];
    if (!s_init) {
        cudaStreamCreateWithFlags(&sW, cudaStreamNonBlocking);
        for (int i = 0; i < KSEG; i++) {
            cudaEventCreateWithFlags(&evG1[i], cudaEventDisableTiming);
            cudaEventCreateWithFlags(&evFc[i], cudaEventDisableTiming);
            cudaEventCreateWithFlags(&evW[i], cudaEventDisableTiming);
        }
        s_init = true;
    }

    cudaFuncSetAttribute(gemm_hf<0, true,  false>, cudaFuncAttributeMaxDynamicSharedMemorySize, GSM_BYTES);
    cudaFuncSetAttribute(gemm_hf<1, true,  true >, cudaFuncAttributeMaxDynamicSharedMemorySize, GSM_BYTES);
    cudaFuncSetAttribute(gemm_hf<1, false, false>, cudaFuncAttributeMaxDynamicSharedMemorySize, GSM_BYTES);
    cudaFuncSetAttribute(gemm_hf<1, false, true >, cudaFuncAttributeMaxDynamicSharedMemorySize, GSM_BYTES);
    cudaFuncSetAttribute(gemm_hf<4, false, false>, cudaFuncAttributeMaxDynamicSharedMemorySize, GSM_BYTES);
    cudaFuncSetAttribute(gemm_hf<5, false, false>, cudaFuncAttributeMaxDynamicSharedMemorySize, GSM_BYTES);
    cudaFuncSetAttribute(wout_lse, cudaFuncAttributeMaxDynamicSharedMemorySize, WOUT_SMEM_BYTES);

    // ---- prologue: conversions / permutations ----
    wperm_kernel<<<(GHC * HC + 255) / 256, 256>>>(Whh0, pWhh0b, HC);
    w1catperm_kernel<<<(GHC * 1024 + 255) / 256, 256>>>(Wih1, Whh1);
    wperm_kernel<<<(GHC * (EC + HC) + 255) / 256, 256>>>(Wih0, pWih0b, EC + HC);
    biasperm_kernel<<<(GHC + 255) / 256, 256>>>(bih0, bhh0, bih1, bhh1);
    cvt_kernel<<<(EC * HC / 4 + 255) / 256, 256>>>(Wfc, pWfcb, EC * HC / 4);
    cvt_kernel<<<(VC * EC / 4 + 255) / 256, 256>>>(Wout, pWoutb, VC * EC / 4);
    cvt_kernel<<<((VC + 2) * EC / 4 + 255) / 256, 256>>>(embed, pembb, (VC + 2) * EC / 4);
    cvt_kernel<<<(HC * UC / 4 + 255) / 256, 256>>>(Wph, pWphb, HC * UC / 4);
    cvt_kernel<<<(T1C * BB * UC / 4 + 255) / 256, 256>>>(encO, pencOb, T1C * BB * UC / 4);

    tok_kernel<<<(GIN_ROWS_PAD + 255) / 256, 256>>>(prev);
    ctxoff_kernel<<<1, 256>>>();
    hcinit_kernel<<<(2 * BB * HC + 255) / 256, 256>>>(encH, encC, Wph, bph, Wpc, bpc);
    initX_kernel<<<(NN * HC) / 256, 256>>>();

    // ctx(fp16) = encO @ Wph^T + bph : M=256, N=512, K=1024 (gather A)
    gemm_hf<1, true, true><<<dim3(512 / 128, 256 / 128), 256, GSM_BYTES>>>(
        pencOb, 0, pWphb, UC, pctxb, HC, UC, pcoff, bph, nullptr, 0, nullptr, nullptr);
    // gctx = ctx @ Wih0p[:,E:]^T + b0p : M=256, N=2048(perm), K=512
    gemm_hf<1, false, false><<<dim3(GHC / 128, 256 / 128), 256, GSM_BYTES>>>(
        pctxb, HC, pWih0b + EC, EC + HC, pgctx, GHC, HC, nullptr, pb0p, nullptr, 0, nullptr, nullptr);
    // gin = emb @ Wih0p[:, :E]^T : M=2432, N=2048(perm), K=256 (gather A)
    gemm_hf<0, true, false><<<dim3(GHC / 128, GIN_ROWS_PAD / 128), 256, GSM_BYTES>>>(
        pembb, 0, pWih0b, EC + HC, pgin, GHC, EC, pgoff, nullptr, nullptr, 0, nullptr, nullptr);

    for (int k = 0; k < KSEG; k++) {
        hf* fcobuf = pfco + (size_t)(k & 1) * NN * EC;
        // layer 0 (s0): g0 = h0 @ Whh0p^T + gin + gctx, fused cell -> c0, h0.
        gemm_hf<4, false, false><<<dim3(GHC / 128, NN / 128), 256, GSM_BYTES>>>(
            pX1, 1024, pWhh0b, HC, nullptr, 0, HC, nullptr, pgin, pgctx, k, pc0, pX1);
        // layer 1 (s0): writes h1 — must wait until fc(k-1) finished READING h1.
        if (k >= 1) cudaStreamWaitEvent(0, evFc[k - 1], 0);
        gemm_hf<5, false, false><<<dim3(GHC / 128, NN / 128), 256, GSM_BYTES>>>(
            pX1, 1024, pW1catb, 1024, nullptr, 0, 1024, nullptr, pb1p, nullptr, k, pc1, pX1 + 512);
        cudaEventRecord(evG1[k], 0);

        // fc(k) + wout(k) on side stream (fco buffer reuse ordered by sW FIFO)
        cudaStreamWaitEvent(sW, evG1[k], 0);
        gemm_hf<1, false, true><<<dim3(EC / 128, NN / 128), 256, GSM_BYTES, sW>>>(
            pX1 + 512, 1024, pWfcb, HC, fcobuf, EC, HC, nullptr, bfc, nullptr, 0, nullptr, nullptr);
        cudaEventRecord(evFc[k], sW);
        wout_lse<<<NN / 64, 256, WOUT_SMEM_BYTES, sW>>>(fcobuf, pWoutb, bout, ptgt, pcum, outp, k);
        cudaEventRecord(evW[k], sW);
    }
    // graph sink must depend on the last wout
    cudaStreamWaitEvent(0, evW[KSEG - 1], 0);
}